// round 9
// baseline (speedup 1.0000x reference)
#include <cuda_runtime.h>
#include <cuda_fp16.h>
#include <math.h>
#include <stdint.h>

// ---------------- problem constants ----------------
#define Bb   256
#define Ss   256
#define Dd   256
#define Hh   4
#define DHh  64
#define Ll   2
#define FF   1024
#define NROWS (Bb*Ss)           // 65536

// ---------------- scratch (__device__ globals; no allocation) ----------------
__device__ __half g_xh [NROWS*Dd];
__device__ __half g_qkv[NROWS*768];
__device__ __half g_ctx[NROWS*Dd];
__device__ __half g_t  [NROWS*Dd];
__device__ __half g_hh [NROWS*Dd];
__device__ __half g_f1 [NROWS*FF];
__device__ __half g_f2 [NROWS*Dd];
// converted weights (transposed to [N][K], half)
__device__ __half g_wqkvt[Ll*768*Dd];
__device__ __half g_wot  [Ll*Dd*Dd];
__device__ __half g_w1t  [Ll*FF*Dd];
__device__ __half g_w2t  [Ll*Dd*FF];
__device__ float  g_bqkv [Ll*768];

// ---------------- helpers ----------------
__device__ __forceinline__ float gelu_exact(float x) {
    return 0.5f * x * (1.0f + erff(x * 0.70710678118654752440f));
}

__device__ __forceinline__ uint32_t smem_u32(const void* p) {
    return (uint32_t)__cvta_generic_to_shared(p);
}

__device__ __forceinline__ void cp_async16(uint32_t dst, const void* src) {
    asm volatile("cp.async.ca.shared.global [%0], [%1], 16;\n"
                 :: "r"(dst), "l"(src));
}
__device__ __forceinline__ void cp_commit() {
    asm volatile("cp.async.commit_group;\n" ::);
}
__device__ __forceinline__ void cp_wait0() {
    asm volatile("cp.async.wait_group 0;\n" ::);
}

__device__ __forceinline__ void mma_f16(float* d, const uint32_t* a, const uint32_t* b) {
    asm volatile(
        "mma.sync.aligned.m16n8k16.row.col.f32.f16.f16.f32 "
        "{%0,%1,%2,%3}, {%4,%5,%6,%7}, {%8,%9}, {%0,%1,%2,%3};"
        : "+f"(d[0]), "+f"(d[1]), "+f"(d[2]), "+f"(d[3])
        : "r"(a[0]), "r"(a[1]), "r"(a[2]), "r"(a[3]), "r"(b[0]), "r"(b[1]));
}

__device__ __forceinline__ uint32_t packh2(float lo, float hi) {
    __half2 h = __floats2half2_rn(lo, hi);
    return *reinterpret_cast<uint32_t*>(&h);
}

// mean + rstd over a 256-wide row, one block of 256 threads
__device__ __forceinline__ float2 rowStats256(float v) {
    float s = v, s2 = v * v;
    #pragma unroll
    for (int o = 16; o > 0; o >>= 1) {
        s  += __shfl_down_sync(0xffffffffu, s,  o);
        s2 += __shfl_down_sync(0xffffffffu, s2, o);
    }
    __shared__ float sh[8], sh2[8];
    int lane = threadIdx.x & 31, wid = threadIdx.x >> 5;
    if (lane == 0) { sh[wid] = s; sh2[wid] = s2; }
    __syncthreads();
    if (threadIdx.x < 32) {
        s  = (lane < 8) ? sh[lane]  : 0.0f;
        s2 = (lane < 8) ? sh2[lane] : 0.0f;
        #pragma unroll
        for (int o = 4; o > 0; o >>= 1) {
            s  += __shfl_down_sync(0xffffffffu, s,  o);
            s2 += __shfl_down_sync(0xffffffffu, s2, o);
        }
        if (lane == 0) { sh[0] = s; sh2[0] = s2; }
    }
    __syncthreads();
    float mu  = sh[0] * (1.0f / 256.0f);
    float var = sh2[0] * (1.0f / 256.0f) - mu * mu;
    return make_float2(mu, rsqrtf(var + 1e-5f));
}

// ---------------- merged weight conversion (ONE launch) ----------------------
// blocks [0, Ll*768): 32x32 transpose tiles; blocks [Ll*768, Ll*768+Ll*3): bias
__global__ void wconv_all_kernel(
        const float* __restrict__ Wq, const float* __restrict__ Wk,
        const float* __restrict__ Wv, const float* __restrict__ Wo,
        const float* __restrict__ W1, const float* __restrict__ W2,
        const float* __restrict__ bq, const float* __restrict__ bk,
        const float* __restrict__ bv,
        __half* __restrict__ wqkvt, __half* __restrict__ wot,
        __half* __restrict__ w1t,   __half* __restrict__ w2t,
        float* __restrict__ bqkv)
{
    int bid = blockIdx.x;
    int tx = threadIdx.x, ty = threadIdx.y;

    if (bid >= Ll * 768) {                    // bias packing
        int idx = bid - Ll * 768;
        int l = idx / 3, t = idx % 3;
        const float* s = (t == 0) ? bq : (t == 1) ? bk : bv;
        int i = ty * 32 + tx;
        bqkv[l * 768 + t * 256 + i] = s[l * 256 + i];
        return;
    }

    int l = bid / 768, r = bid % 768;
    const float* in; __half* out; int K, N, ti;
    if      (r < 64)  { in = Wq + (long)l*Dd*Dd; out = wqkvt + (long)l*768*Dd;            K = Dd; N = Dd; ti = r; }
    else if (r < 128) { in = Wk + (long)l*Dd*Dd; out = wqkvt + (long)l*768*Dd + 256*Dd;   K = Dd; N = Dd; ti = r - 64; }
    else if (r < 192) { in = Wv + (long)l*Dd*Dd; out = wqkvt + (long)l*768*Dd + 512*Dd;   K = Dd; N = Dd; ti = r - 128; }
    else if (r < 256) { in = Wo + (long)l*Dd*Dd; out = wot + (long)l*Dd*Dd;               K = Dd; N = Dd; ti = r - 192; }
    else if (r < 512) { in = W1 + (long)l*Dd*FF; out = w1t + (long)l*FF*Dd;               K = Dd; N = FF; ti = r - 256; }
    else              { in = W2 + (long)l*FF*Dd; out = w2t + (long)l*Dd*FF;               K = FF; N = Dd; ti = r - 512; }

    int ntx = N / 32;
    int n0 = (ti % ntx) * 32, k0 = (ti / ntx) * 32;

    __shared__ float t[32][33];
    #pragma unroll
    for (int i = 0; i < 32; i += 8)
        t[ty + i][tx] = in[(long)(k0 + ty + i) * N + n0 + tx];
    __syncthreads();
    #pragma unroll
    for (int i = 0; i < 32; i += 8)
        out[(long)(n0 + ty + i) * K + k0 + tx] = __float2half_rn(t[tx][ty + i]);
}

// ---------------- kernel 1: embedding + LN (also init total) ----------------
__global__ void __launch_bounds__(256) embed_ln_kernel(
        const int* __restrict__ ids,
        const float* __restrict__ item_emb,
        const float* __restrict__ pos_emb,
        __half* __restrict__ x, float* __restrict__ out)
{
    int row = blockIdx.x;
    int t   = threadIdx.x;
    int s   = row & (Ss - 1);
    int id  = ids[row];
    float v = item_emb[(long)id * Dd + t] + pos_emb[s * Dd + t];
    float2 st = rowStats256(v);
    float y = (v - st.x) * st.y;
    long o = (long)row * Dd + t;
    x[o] = __float2half_rn(y);
    out[o] = y;
}

// ---------------- kernel 2: fp16 GEMM, cp.async 2-stage pipeline -------------
// C(half)[M][N] = A(half)[M][K] @ Wt(half)[N][K]^T + bias(f32), optional GELU.
// BM=BN=128, BK=32, 256 threads (8 warps 4m x 2n), warp tile 32x64.
#define HS 40   // smem stride in halves; fragment banks (20g+tig)%32 all-distinct

__global__ void __launch_bounds__(256, 2) gemm_f16_kernel(
        const __half* __restrict__ A, const __half* __restrict__ Wt,
        const float* __restrict__ bias, __half* __restrict__ C,
        int N, int K, int act)
{
    __shared__ __half As[2][128 * HS];
    __shared__ __half Bs[2][128 * HS];

    int tid  = threadIdx.x;
    int w    = tid >> 5, lane = tid & 31;
    int g    = lane >> 2, tig = lane & 3;
    int wm   = w >> 1,  wn = w & 1;
    int rowb = blockIdx.y * 128;
    int colb = blockIdx.x * 128;

    // async-copy chunk mapping: 512 16B-chunks per tile, 2 per thread
    int c0 = tid * 2;
    int rA0 = c0 >> 2,        oA0 = (c0 & 3) * 8;
    int rA1 = (c0 + 1) >> 2,  oA1 = ((c0 + 1) & 3) * 8;

    const __half* Abase = A  + (long)rowb * K;
    const __half* Wbase = Wt + (long)colb * K;

    float acc[2][8][4];
    #pragma unroll
    for (int mt = 0; mt < 2; mt++)
        #pragma unroll
        for (int nt = 0; nt < 8; nt++)
            #pragma unroll
            for (int r = 0; r < 4; r++) acc[mt][nt][r] = 0.0f;

    // ---- preload stage 0 ----
    {
        cp_async16(smem_u32(&As[0][rA0 * HS + oA0]), Abase + (long)rA0 * K + oA0);
        cp_async16(smem_u32(&As[0][rA1 * HS + oA1]), Abase + (long)rA1 * K + oA1);
        cp_async16(smem_u32(&Bs[0][rA0 * HS + oA0]), Wbase + (long)rA0 * K + oA0);
        cp_async16(smem_u32(&Bs[0][rA1 * HS + oA1]), Wbase + (long)rA1 * K + oA1);
        cp_commit();
    }

    int nk = K >> 5;
    for (int it = 0; it < nk; it++) {
        cp_wait0();
        __syncthreads();

        if (it + 1 < nk) {
            int buf = (it + 1) & 1, kt = (it + 1) * 32;
            cp_async16(smem_u32(&As[buf][rA0 * HS + oA0]), Abase + (long)rA0 * K + kt + oA0);
            cp_async16(smem_u32(&As[buf][rA1 * HS + oA1]), Abase + (long)rA1 * K + kt + oA1);
            cp_async16(smem_u32(&Bs[buf][rA0 * HS + oA0]), Wbase + (long)rA0 * K + kt + oA0);
            cp_async16(smem_u32(&Bs[buf][rA1 * HS + oA1]), Wbase + (long)rA1 * K + kt + oA1);
            cp_commit();
        }

        int buf = it & 1;
        #pragma unroll
        for (int ks = 0; ks < 2; ks++) {
            int k0 = ks * 16;
            uint32_t a[2][4], b[8][2];
            #pragma unroll
            for (int mt = 0; mt < 2; mt++) {
                int r0 = wm * 32 + mt * 16 + g;
                a[mt][0] = *(const uint32_t*)&As[buf][ r0      * HS + k0 + 2 * tig];
                a[mt][1] = *(const uint32_t*)&As[buf][(r0 + 8) * HS + k0 + 2 * tig];
                a[mt][2] = *(const uint32_t*)&As[buf][ r0      * HS + k0 + 8 + 2 * tig];
                a[mt][3] = *(const uint32_t*)&As[buf][(r0 + 8) * HS + k0 + 8 + 2 * tig];
            }
            #pragma unroll
            for (int nt = 0; nt < 8; nt++) {
                int n = wn * 64 + nt * 8 + g;
                b[nt][0] = *(const uint32_t*)&Bs[buf][n * HS + k0 + 2 * tig];
                b[nt][1] = *(const uint32_t*)&Bs[buf][n * HS + k0 + 8 + 2 * tig];
            }
            #pragma unroll
            for (int mt = 0; mt < 2; mt++)
                #pragma unroll
                for (int nt = 0; nt < 8; nt++)
                    mma_f16(acc[mt][nt], a[mt], b[nt]);
        }
        __syncthreads();
    }

    #pragma unroll
    for (int mt = 0; mt < 2; mt++) {
        int row0 = rowb + wm * 32 + mt * 16 + g;
        #pragma unroll
        for (int nt = 0; nt < 8; nt++) {
            int col = colb + wn * 64 + nt * 8 + 2 * tig;
            float b0 = bias[col], b1 = bias[col + 1];
            float o0 = acc[mt][nt][0] + b0;
            float o1 = acc[mt][nt][1] + b1;
            float o2 = acc[mt][nt][2] + b0;
            float o3 = acc[mt][nt][3] + b1;
            if (act) { o0 = gelu_exact(o0); o1 = gelu_exact(o1);
                       o2 = gelu_exact(o2); o3 = gelu_exact(o3); }
            *(__half2*)&C[(long)row0 * N + col]       = __floats2half2_rn(o0, o1);
            *(__half2*)&C[(long)(row0 + 8) * N + col] = __floats2half2_rn(o2, o3);
        }
    }
}

// ---------------- kernel 3: fused fp16 attention, explicit LDS frags ---------
// (unchanged from R7 — passes at 5.3e-4)
#define AS 72
#define VTS 264
#define ATTN_SMEM ((2 * Ss * AS + DHh * VTS) * 2 + Ss * 4)

__global__ void __launch_bounds__(256, 1) attn_f16_kernel(
        const __half* __restrict__ qkv, const int* __restrict__ ids,
        __half* __restrict__ ctx)
{
    extern __shared__ char smraw[];
    __half* sQ  = (__half*)smraw;            // 256 x 72
    __half* sK  = sQ + Ss * AS;              // 256 x 72
    __half* sVt = sK + Ss * AS;              // 64 x 264  (sVt[d][key])
    float* sBias = (float*)(sVt + DHh * VTS);

    int bh = blockIdx.x;
    int b = bh >> 2, h = bh & 3;
    int base = b * Ss, hoff = h * DHh;
    int tid = threadIdx.x;

    for (int idx = tid; idx < Ss * 8; idx += 256) {
        int r = idx >> 3, u = idx & 7;
        const __half* gp = qkv + (long)(base + r) * 768 + hoff + u * 8;
        *(uint4*)&sQ[r * AS + u * 8] = *(const uint4*)(gp);
        *(uint4*)&sK[r * AS + u * 8] = *(const uint4*)(gp + 256);
    }
    for (int idx = tid; idx < Ss * DHh; idx += 256) {
        int r = idx >> 6, d = idx & 63;
        sVt[d * VTS + r] = qkv[(long)(base + r) * 768 + 512 + hoff + d];
    }
    if (tid < Ss) sBias[tid] = (ids[base + tid] > 0) ? 0.0f : -10000.0f;
    __syncthreads();

    int w = tid >> 5, lane = tid & 31;
    int g = lane >> 2, tig = lane & 3;
    const float scale = 0.125f;

    for (int pass = 0; pass < 2; pass++) {
        int m0 = pass * 128 + w * 16;
        int r0 = m0 + g, r1 = m0 + 8 + g;

        uint32_t aS[4][4];
        #pragma unroll
        for (int kc = 0; kc < 4; kc++) {
            int c = kc * 16 + 2 * tig;
            aS[kc][0] = *(const uint32_t*)&sQ[ r0 * AS + c];
            aS[kc][1] = *(const uint32_t*)&sQ[ r1 * AS + c];
            aS[kc][2] = *(const uint32_t*)&sQ[ r0 * AS + c + 8];
            aS[kc][3] = *(const uint32_t*)&sQ[ r1 * AS + c + 8];
        }

        float acc[32][4];
        #pragma unroll
        for (int nt = 0; nt < 32; nt++)
            #pragma unroll
            for (int r = 0; r < 4; r++) acc[nt][r] = 0.0f;

        #pragma unroll
        for (int kc = 0; kc < 4; kc++) {
            int c = kc * 16 + 2 * tig;
            #pragma unroll
            for (int nt = 0; nt < 32; nt++) {
                int n = nt * 8 + g;
                uint32_t bb[2];
                bb[0] = *(const uint32_t*)&sK[n * AS + c];
                bb[1] = *(const uint32_t*)&sK[n * AS + c + 8];
                mma_f16(acc[nt], aS[kc], bb);
            }
        }

        float mx0 = -1e30f, mx1 = -1e30f;
        #pragma unroll
        for (int nt = 0; nt < 32; nt++) {
            int c0 = nt * 8 + 2 * tig, c1 = c0 + 1;
            float bp0 = sBias[c0], bp1 = sBias[c1];
            acc[nt][0] = acc[nt][0] * scale + ((c0 <= r0) ? bp0 : -10000.0f);
            acc[nt][1] = acc[nt][1] * scale + ((c1 <= r0) ? bp1 : -10000.0f);
            acc[nt][2] = acc[nt][2] * scale + ((c0 <= r1) ? bp0 : -10000.0f);
            acc[nt][3] = acc[nt][3] * scale + ((c1 <= r1) ? bp1 : -10000.0f);
            mx0 = fmaxf(mx0, fmaxf(acc[nt][0], acc[nt][1]));
            mx1 = fmaxf(mx1, fmaxf(acc[nt][2], acc[nt][3]));
        }
        mx0 = fmaxf(mx0, __shfl_xor_sync(0xffffffffu, mx0, 1));
        mx0 = fmaxf(mx0, __shfl_xor_sync(0xffffffffu, mx0, 2));
        mx1 = fmaxf(mx1, __shfl_xor_sync(0xffffffffu, mx1, 1));
        mx1 = fmaxf(mx1, __shfl_xor_sync(0xffffffffu, mx1, 2));

        float s0 = 0.0f, s1 = 0.0f;
        #pragma unroll
        for (int nt = 0; nt < 32; nt++) {
            acc[nt][0] = __expf(acc[nt][0] - mx0);
            acc[nt][1] = __expf(acc[nt][1] - mx0);
            acc[nt][2] = __expf(acc[nt][2] - mx1);
            acc[nt][3] = __expf(acc[nt][3] - mx1);
            s0 += acc[nt][0] + acc[nt][1];
            s1 += acc[nt][2] + acc[nt][3];
        }
        s0 += __shfl_xor_sync(0xffffffffu, s0, 1);
        s0 += __shfl_xor_sync(0xffffffffu, s0, 2);
        s1 += __shfl_xor_sync(0xffffffffu, s1, 1);
        s1 += __shfl_xor_sync(0xffffffffu, s1, 2);
        float i0 = 1.0f / s0, i1 = 1.0f / s1;

        float acc2[8][4];
        #pragma unroll
        for (int nt = 0; nt < 8; nt++)
            #pragma unroll
            for (int r = 0; r < 4; r++) acc2[nt][r] = 0.0f;

        #pragma unroll
        for (int kc = 0; kc < 16; kc++) {
            uint32_t a[4];
            a[0] = packh2(acc[2*kc][0]   * i0, acc[2*kc][1]   * i0);
            a[1] = packh2(acc[2*kc][2]   * i1, acc[2*kc][3]   * i1);
            a[2] = packh2(acc[2*kc+1][0] * i0, acc[2*kc+1][1] * i0);
            a[3] = packh2(acc[2*kc+1][2] * i1, acc[2*kc+1][3] * i1);
            int c = kc * 16 + 2 * tig;
            #pragma unroll
            for (int nt = 0; nt < 8; nt++) {
                int d = nt * 8 + g;
                uint32_t bb[2];
                bb[0] = *(const uint32_t*)&sVt[d * VTS + c];
                bb[1] = *(const uint32_t*)&sVt[d * VTS + c + 8];
                mma_f16(acc2[nt], a, bb);
            }
        }

        long o0 = (long)(base + r0) * Dd + hoff;
        long o1 = (long)(base + r1) * Dd + hoff;
        #pragma unroll
        for (int nt = 0; nt < 8; nt++) {
            int d = nt * 8 + 2 * tig;
            *(__half2*)&ctx[o0 + d] = __floats2half2_rn(acc2[nt][0], acc2[nt][1]);
            *(__half2*)&ctx[o1 + d] = __floats2half2_rn(acc2[nt][2], acc2[nt][3]);
        }
    }
}

// ---------------- kernel 4: h = LN(t + x) (half io) ----------------
__global__ void __launch_bounds__(256) add_ln_kernel(
        const __half* __restrict__ a, const __half* __restrict__ bres,
        __half* __restrict__ out)
{
    long i = (long)blockIdx.x * Dd + threadIdx.x;
    float v = __half2float(a[i]) + __half2float(bres[i]);
    float2 st = rowStats256(v);
    out[i] = __float2half_rn((v - st.x) * st.y);
}

// ---------------- kernel 5: x = LN(f2); total += x ----------------
__global__ void __launch_bounds__(256) ln_acc_kernel(
        const __half* __restrict__ f2, __half* __restrict__ x,
        float* __restrict__ out)
{
    long i = (long)blockIdx.x * Dd + threadIdx.x;
    float v = __half2float(f2[i]);
    float2 st = rowStats256(v);
    float y = (v - st.x) * st.y;
    x[i] = __float2half_rn(y);
    out[i] += y;
}

// ---------------- launch ----------------
extern "C" void kernel_launch(void* const* d_in, const int* in_sizes, int n_in,
                              void* d_out, int out_size)
{
    const int*   ids      = (const int*)  d_in[0];
    const float* item_emb = (const float*)d_in[1];
    const float* pos_emb  = (const float*)d_in[2];
    const float* Wq = (const float*)d_in[3];  const float* bq = (const float*)d_in[4];
    const float* Wk = (const float*)d_in[5];  const float* bk = (const float*)d_in[6];
    const float* Wv = (const float*)d_in[7];  const float* bv = (const float*)d_in[8];
    const float* Wo = (const float*)d_in[9];  const float* bo = (const float*)d_in[10];
    const float* W1 = (const float*)d_in[11]; const float* b1 = (const float*)d_in[12];
    const float* W2 = (const float*)d_in[13]; const float* b2 = (const float*)d_in[14];
    float* out = (float*)d_out;

    __half *x, *qkv, *ctx, *t, *h, *f1, *f2;
    __half *wqkvt, *wot, *w1t, *w2t;
    float  *bqkv;
    cudaGetSymbolAddress((void**)&x,     g_xh);
    cudaGetSymbolAddress((void**)&qkv,   g_qkv);
    cudaGetSymbolAddress((void**)&ctx,   g_ctx);
    cudaGetSymbolAddress((void**)&t,     g_t);
    cudaGetSymbolAddress((void**)&h,     g_hh);
    cudaGetSymbolAddress((void**)&f1,    g_f1);
    cudaGetSymbolAddress((void**)&f2,    g_f2);
    cudaGetSymbolAddress((void**)&wqkvt, g_wqkvt);
    cudaGetSymbolAddress((void**)&wot,   g_wot);
    cudaGetSymbolAddress((void**)&w1t,   g_w1t);
    cudaGetSymbolAddress((void**)&w2t,   g_w2t);
    cudaGetSymbolAddress((void**)&bqkv,  g_bqkv);

    cudaFuncSetAttribute(attn_f16_kernel,
                         cudaFuncAttributeMaxDynamicSharedMemorySize, ATTN_SMEM);

    // ---- one-launch weight conversion + bias packing ----
    wconv_all_kernel<<<Ll * 768 + Ll * 3, dim3(32, 8)>>>(
        Wq, Wk, Wv, Wo, W1, W2, bq, bk, bv, wqkvt, wot, w1t, w2t, bqkv);

    embed_ln_kernel<<<NROWS, 256>>>(ids, item_emb, pos_emb, x, out);

    dim3 gQKV(6, 512), gD(2, 512), gF(8, 512);

    for (int l = 0; l < Ll; l++) {
        gemm_f16_kernel<<<gQKV, 256>>>(x, wqkvt + (long)l*768*Dd, bqkv + l*768,
                                       qkv, 768, Dd, 0);

        attn_f16_kernel<<<Bb * Hh, 256, ATTN_SMEM>>>(qkv, ids, ctx);

        gemm_f16_kernel<<<gD, 256>>>(ctx, wot + (long)l*Dd*Dd, bo + l*Dd,
                                     t, Dd, Dd, 0);
        add_ln_kernel<<<NROWS, 256>>>(t, x, h);

        gemm_f16_kernel<<<gF, 256>>>(h, w1t + (long)l*FF*Dd, b1 + l*FF,
                                     f1, FF, Dd, 1);
        gemm_f16_kernel<<<gD, 256>>>(f1, w2t + (long)l*Dd*FF, b2 + l*Dd,
                                     f2, Dd, FF, 0);

        ln_acc_kernel<<<NROWS, 256>>>(f2, x, out);
    }
}

// round 11
// speedup vs baseline: 1.4177x; 1.4177x over previous
#include <cuda_runtime.h>
#include <cuda_fp16.h>
#include <math.h>
#include <stdint.h>

// ---------------- problem constants ----------------
#define Bb   256
#define Ss   256
#define Dd   256
#define Hh   4
#define DHh  64
#define Ll   2
#define FF   1024
#define NROWS (Bb*Ss)           // 65536

// ---------------- scratch (__device__ globals; no allocation) ----------------
__device__ __half g_xh [NROWS*Dd];
__device__ __half g_qkv[NROWS*768];
__device__ __half g_ctx[NROWS*Dd];
__device__ __half g_t  [NROWS*Dd];
__device__ __half g_hh [NROWS*Dd];
__device__ __half g_f1 [NROWS*FF];
__device__ __half g_f2 [NROWS*Dd];
// converted weights (transposed to [N][K], half)
__device__ __half g_wqkvt[Ll*768*Dd];
__device__ __half g_wot  [Ll*Dd*Dd];
__device__ __half g_w1t  [Ll*FF*Dd];
__device__ __half g_w2t  [Ll*Dd*FF];
__device__ float  g_bqkv [Ll*768];

// ---------------- helpers ----------------
__device__ __forceinline__ float gelu_exact(float x) {
    return 0.5f * x * (1.0f + erff(x * 0.70710678118654752440f));
}

__device__ __forceinline__ void mma_f16(float* d, const uint32_t* a, const uint32_t* b) {
    asm volatile(
        "mma.sync.aligned.m16n8k16.row.col.f32.f16.f16.f32 "
        "{%0,%1,%2,%3}, {%4,%5,%6,%7}, {%8,%9}, {%0,%1,%2,%3};"
        : "+f"(d[0]), "+f"(d[1]), "+f"(d[2]), "+f"(d[3])
        : "r"(a[0]), "r"(a[1]), "r"(a[2]), "r"(a[3]), "r"(b[0]), "r"(b[1]));
}

__device__ __forceinline__ uint32_t packh2(float lo, float hi) {
    __half2 h = __floats2half2_rn(lo, hi);
    return *reinterpret_cast<uint32_t*>(&h);
}

// mean + rstd over a 256-wide row, one block of 256 threads
__device__ __forceinline__ float2 rowStats256(float v) {
    float s = v, s2 = v * v;
    #pragma unroll
    for (int o = 16; o > 0; o >>= 1) {
        s  += __shfl_down_sync(0xffffffffu, s,  o);
        s2 += __shfl_down_sync(0xffffffffu, s2, o);
    }
    __shared__ float sh[8], sh2[8];
    int lane = threadIdx.x & 31, wid = threadIdx.x >> 5;
    if (lane == 0) { sh[wid] = s; sh2[wid] = s2; }
    __syncthreads();
    if (threadIdx.x < 32) {
        s  = (lane < 8) ? sh[lane]  : 0.0f;
        s2 = (lane < 8) ? sh2[lane] : 0.0f;
        #pragma unroll
        for (int o = 4; o > 0; o >>= 1) {
            s  += __shfl_down_sync(0xffffffffu, s,  o);
            s2 += __shfl_down_sync(0xffffffffu, s2, o);
        }
        if (lane == 0) { sh[0] = s; sh2[0] = s2; }
    }
    __syncthreads();
    float mu  = sh[0] * (1.0f / 256.0f);
    float var = sh2[0] * (1.0f / 256.0f) - mu * mu;
    return make_float2(mu, rsqrtf(var + 1e-5f));
}

// ---------------- merged weight conversion (ONE launch) ----------------------
__global__ void wconv_all_kernel(
        const float* __restrict__ Wq, const float* __restrict__ Wk,
        const float* __restrict__ Wv, const float* __restrict__ Wo,
        const float* __restrict__ W1, const float* __restrict__ W2,
        const float* __restrict__ bq, const float* __restrict__ bk,
        const float* __restrict__ bv,
        __half* __restrict__ wqkvt, __half* __restrict__ wot,
        __half* __restrict__ w1t,   __half* __restrict__ w2t,
        float* __restrict__ bqkv)
{
    int bid = blockIdx.x;
    int tx = threadIdx.x, ty = threadIdx.y;

    if (bid >= Ll * 768) {                    // bias packing
        int idx = bid - Ll * 768;
        int l = idx / 3, t = idx % 3;
        const float* s = (t == 0) ? bq : (t == 1) ? bk : bv;
        int i = ty * 32 + tx;
        bqkv[l * 768 + t * 256 + i] = s[l * 256 + i];
        return;
    }

    int l = bid / 768, r = bid % 768;
    const float* in; __half* out; int K, N, ti;
    if      (r < 64)  { in = Wq + (long)l*Dd*Dd; out = wqkvt + (long)l*768*Dd;            K = Dd; N = Dd; ti = r; }
    else if (r < 128) { in = Wk + (long)l*Dd*Dd; out = wqkvt + (long)l*768*Dd + 256*Dd;   K = Dd; N = Dd; ti = r - 64; }
    else if (r < 192) { in = Wv + (long)l*Dd*Dd; out = wqkvt + (long)l*768*Dd + 512*Dd;   K = Dd; N = Dd; ti = r - 128; }
    else if (r < 256) { in = Wo + (long)l*Dd*Dd; out = wot + (long)l*Dd*Dd;               K = Dd; N = Dd; ti = r - 192; }
    else if (r < 512) { in = W1 + (long)l*Dd*FF; out = w1t + (long)l*FF*Dd;               K = Dd; N = FF; ti = r - 256; }
    else              { in = W2 + (long)l*FF*Dd; out = w2t + (long)l*Dd*FF;               K = FF; N = Dd; ti = r - 512; }

    int ntx = N / 32;
    int n0 = (ti % ntx) * 32, k0 = (ti / ntx) * 32;

    __shared__ float t[32][33];
    #pragma unroll
    for (int i = 0; i < 32; i += 8)
        t[ty + i][tx] = in[(long)(k0 + ty + i) * N + n0 + tx];
    __syncthreads();
    #pragma unroll
    for (int i = 0; i < 32; i += 8)
        out[(long)(n0 + ty + i) * K + k0 + tx] = __float2half_rn(t[tx][ty + i]);
}

// ---------------- kernel 1: embedding + LN (also init total) ----------------
__global__ void __launch_bounds__(256) embed_ln_kernel(
        const int* __restrict__ ids,
        const float* __restrict__ item_emb,
        const float* __restrict__ pos_emb,
        __half* __restrict__ x, float* __restrict__ out)
{
    int row = blockIdx.x;
    int t   = threadIdx.x;
    int s   = row & (Ss - 1);
    int id  = ids[row];
    float v = item_emb[(long)id * Dd + t] + pos_emb[s * Dd + t];
    float2 st = rowStats256(v);
    float y = (v - st.x) * st.y;
    long o = (long)row * Dd + t;
    x[o] = __float2half_rn(y);
    out[o] = y;
}

// ---------------- kernel 2: fp16 GEMM, explicit LDS fragments (R7 winner) ----
// C(half)[M][N] = A(half)[M][K] @ Wt(half)[N][K]^T + bias(f32), optional GELU.
// BM=BN=128, BK=32, 256 threads (8 warps 4m x 2n), warp tile 32x64.
// Synchronous uint4 loads; single-buffer 20KB smem -> multi-block co-residency
// does the latency hiding (R8's cp.async pipeline regressed this).
#define HS 40   // smem stride in halves; fragment banks (20g+tig)%32 all-distinct

__global__ void __launch_bounds__(256) gemm_f16_kernel(
        const __half* __restrict__ A, const __half* __restrict__ Wt,
        const float* __restrict__ bias, __half* __restrict__ C,
        int N, int K, int act)
{
    __shared__ __half As[128 * HS];
    __shared__ __half Bs[128 * HS];

    int tid  = threadIdx.x;
    int w    = tid >> 5, lane = tid & 31;
    int g    = lane >> 2, tig = lane & 3;
    int wm   = w >> 1,  wn = w & 1;
    int rowb = blockIdx.y * 128;
    int colb = blockIdx.x * 128;

    int sr = tid >> 1, sc = (tid & 1) * 16;
    const __half* Ag = A  + (long)(rowb + sr) * K + sc;
    const __half* Wg = Wt + (long)(colb + sr) * K + sc;

    float acc[2][8][4];
    #pragma unroll
    for (int mt = 0; mt < 2; mt++)
        #pragma unroll
        for (int nt = 0; nt < 8; nt++)
            #pragma unroll
            for (int r = 0; r < 4; r++) acc[mt][nt][r] = 0.0f;

    for (int kt = 0; kt < K; kt += 32) {
        __syncthreads();
        uint4 av0 = *(const uint4*)(Ag + kt);
        uint4 av1 = *(const uint4*)(Ag + kt + 8);
        uint4 wv0 = *(const uint4*)(Wg + kt);
        uint4 wv1 = *(const uint4*)(Wg + kt + 8);
        *(uint4*)&As[sr * HS + sc]     = av0;
        *(uint4*)&As[sr * HS + sc + 8] = av1;
        *(uint4*)&Bs[sr * HS + sc]     = wv0;
        *(uint4*)&Bs[sr * HS + sc + 8] = wv1;
        __syncthreads();

        #pragma unroll
        for (int ks = 0; ks < 2; ks++) {
            int k0 = ks * 16;
            uint32_t a[2][4], b[8][2];
            #pragma unroll
            for (int mt = 0; mt < 2; mt++) {
                int r0 = wm * 32 + mt * 16 + g;
                a[mt][0] = *(const uint32_t*)&As[ r0      * HS + k0 + 2 * tig];
                a[mt][1] = *(const uint32_t*)&As[(r0 + 8) * HS + k0 + 2 * tig];
                a[mt][2] = *(const uint32_t*)&As[ r0      * HS + k0 + 8 + 2 * tig];
                a[mt][3] = *(const uint32_t*)&As[(r0 + 8) * HS + k0 + 8 + 2 * tig];
            }
            #pragma unroll
            for (int nt = 0; nt < 8; nt++) {
                int n = wn * 64 + nt * 8 + g;
                b[nt][0] = *(const uint32_t*)&Bs[n * HS + k0 + 2 * tig];
                b[nt][1] = *(const uint32_t*)&Bs[n * HS + k0 + 8 + 2 * tig];
            }
            #pragma unroll
            for (int mt = 0; mt < 2; mt++)
                #pragma unroll
                for (int nt = 0; nt < 8; nt++)
                    mma_f16(acc[mt][nt], a[mt], b[nt]);
        }
    }

    #pragma unroll
    for (int mt = 0; mt < 2; mt++) {
        int row0 = rowb + wm * 32 + mt * 16 + g;
        #pragma unroll
        for (int nt = 0; nt < 8; nt++) {
            int col = colb + wn * 64 + nt * 8 + 2 * tig;
            float b0 = bias[col], b1 = bias[col + 1];
            float o0 = acc[mt][nt][0] + b0;
            float o1 = acc[mt][nt][1] + b1;
            float o2 = acc[mt][nt][2] + b0;
            float o3 = acc[mt][nt][3] + b1;
            if (act) { o0 = gelu_exact(o0); o1 = gelu_exact(o1);
                       o2 = gelu_exact(o2); o3 = gelu_exact(o3); }
            *(__half2*)&C[(long)row0 * N + col]       = __floats2half2_rn(o0, o1);
            *(__half2*)&C[(long)(row0 + 8) * N + col] = __floats2half2_rn(o2, o3);
        }
    }
}

// ---------------- kernel 3: fused fp16 attention (R7, unchanged) -------------
#define AS 72
#define VTS 264
#define ATTN_SMEM ((2 * Ss * AS + DHh * VTS) * 2 + Ss * 4)

__global__ void __launch_bounds__(256, 1) attn_f16_kernel(
        const __half* __restrict__ qkv, const int* __restrict__ ids,
        __half* __restrict__ ctx)
{
    extern __shared__ char smraw[];
    __half* sQ  = (__half*)smraw;            // 256 x 72
    __half* sK  = sQ + Ss * AS;              // 256 x 72
    __half* sVt = sK + Ss * AS;              // 64 x 264  (sVt[d][key])
    float* sBias = (float*)(sVt + DHh * VTS);

    int bh = blockIdx.x;
    int b = bh >> 2, h = bh & 3;
    int base = b * Ss, hoff = h * DHh;
    int tid = threadIdx.x;

    for (int idx = tid; idx < Ss * 8; idx += 256) {
        int r = idx >> 3, u = idx & 7;
        const __half* gp = qkv + (long)(base + r) * 768 + hoff + u * 8;
        *(uint4*)&sQ[r * AS + u * 8] = *(const uint4*)(gp);
        *(uint4*)&sK[r * AS + u * 8] = *(const uint4*)(gp + 256);
    }
    for (int idx = tid; idx < Ss * DHh; idx += 256) {
        int r = idx >> 6, d = idx & 63;
        sVt[d * VTS + r] = qkv[(long)(base + r) * 768 + 512 + hoff + d];
    }
    if (tid < Ss) sBias[tid] = (ids[base + tid] > 0) ? 0.0f : -10000.0f;
    __syncthreads();

    int w = tid >> 5, lane = tid & 31;
    int g = lane >> 2, tig = lane & 3;
    const float scale = 0.125f;

    for (int pass = 0; pass < 2; pass++) {
        int m0 = pass * 128 + w * 16;
        int r0 = m0 + g, r1 = m0 + 8 + g;

        uint32_t aS[4][4];
        #pragma unroll
        for (int kc = 0; kc < 4; kc++) {
            int c = kc * 16 + 2 * tig;
            aS[kc][0] = *(const uint32_t*)&sQ[ r0 * AS + c];
            aS[kc][1] = *(const uint32_t*)&sQ[ r1 * AS + c];
            aS[kc][2] = *(const uint32_t*)&sQ[ r0 * AS + c + 8];
            aS[kc][3] = *(const uint32_t*)&sQ[ r1 * AS + c + 8];
        }

        float acc[32][4];
        #pragma unroll
        for (int nt = 0; nt < 32; nt++)
            #pragma unroll
            for (int r = 0; r < 4; r++) acc[nt][r] = 0.0f;

        #pragma unroll
        for (int kc = 0; kc < 4; kc++) {
            int c = kc * 16 + 2 * tig;
            #pragma unroll
            for (int nt = 0; nt < 32; nt++) {
                int n = nt * 8 + g;
                uint32_t bb[2];
                bb[0] = *(const uint32_t*)&sK[n * AS + c];
                bb[1] = *(const uint32_t*)&sK[n * AS + c + 8];
                mma_f16(acc[nt], aS[kc], bb);
            }
        }

        float mx0 = -1e30f, mx1 = -1e30f;
        #pragma unroll
        for (int nt = 0; nt < 32; nt++) {
            int c0 = nt * 8 + 2 * tig, c1 = c0 + 1;
            float bp0 = sBias[c0], bp1 = sBias[c1];
            acc[nt][0] = acc[nt][0] * scale + ((c0 <= r0) ? bp0 : -10000.0f);
            acc[nt][1] = acc[nt][1] * scale + ((c1 <= r0) ? bp1 : -10000.0f);
            acc[nt][2] = acc[nt][2] * scale + ((c0 <= r1) ? bp0 : -10000.0f);
            acc[nt][3] = acc[nt][3] * scale + ((c1 <= r1) ? bp1 : -10000.0f);
            mx0 = fmaxf(mx0, fmaxf(acc[nt][0], acc[nt][1]));
            mx1 = fmaxf(mx1, fmaxf(acc[nt][2], acc[nt][3]));
        }
        mx0 = fmaxf(mx0, __shfl_xor_sync(0xffffffffu, mx0, 1));
        mx0 = fmaxf(mx0, __shfl_xor_sync(0xffffffffu, mx0, 2));
        mx1 = fmaxf(mx1, __shfl_xor_sync(0xffffffffu, mx1, 1));
        mx1 = fmaxf(mx1, __shfl_xor_sync(0xffffffffu, mx1, 2));

        float s0 = 0.0f, s1 = 0.0f;
        #pragma unroll
        for (int nt = 0; nt < 32; nt++) {
            acc[nt][0] = __expf(acc[nt][0] - mx0);
            acc[nt][1] = __expf(acc[nt][1] - mx0);
            acc[nt][2] = __expf(acc[nt][2] - mx1);
            acc[nt][3] = __expf(acc[nt][3] - mx1);
            s0 += acc[nt][0] + acc[nt][1];
            s1 += acc[nt][2] + acc[nt][3];
        }
        s0 += __shfl_xor_sync(0xffffffffu, s0, 1);
        s0 += __shfl_xor_sync(0xffffffffu, s0, 2);
        s1 += __shfl_xor_sync(0xffffffffu, s1, 1);
        s1 += __shfl_xor_sync(0xffffffffu, s1, 2);
        float i0 = 1.0f / s0, i1 = 1.0f / s1;

        float acc2[8][4];
        #pragma unroll
        for (int nt = 0; nt < 8; nt++)
            #pragma unroll
            for (int r = 0; r < 4; r++) acc2[nt][r] = 0.0f;

        #pragma unroll
        for (int kc = 0; kc < 16; kc++) {
            uint32_t a[4];
            a[0] = packh2(acc[2*kc][0]   * i0, acc[2*kc][1]   * i0);
            a[1] = packh2(acc[2*kc][2]   * i1, acc[2*kc][3]   * i1);
            a[2] = packh2(acc[2*kc+1][0] * i0, acc[2*kc+1][1] * i0);
            a[3] = packh2(acc[2*kc+1][2] * i1, acc[2*kc+1][3] * i1);
            int c = kc * 16 + 2 * tig;
            #pragma unroll
            for (int nt = 0; nt < 8; nt++) {
                int d = nt * 8 + g;
                uint32_t bb[2];
                bb[0] = *(const uint32_t*)&sVt[d * VTS + c];
                bb[1] = *(const uint32_t*)&sVt[d * VTS + c + 8];
                mma_f16(acc2[nt], a, bb);
            }
        }

        long o0 = (long)(base + r0) * Dd + hoff;
        long o1 = (long)(base + r1) * Dd + hoff;
        #pragma unroll
        for (int nt = 0; nt < 8; nt++) {
            int d = nt * 8 + 2 * tig;
            *(__half2*)&ctx[o0 + d] = __floats2half2_rn(acc2[nt][0], acc2[nt][1]);
            *(__half2*)&ctx[o1 + d] = __floats2half2_rn(acc2[nt][2], acc2[nt][3]);
        }
    }
}

// ---------------- kernel 4: h = LN(t + x) (half io) ----------------
__global__ void __launch_bounds__(256) add_ln_kernel(
        const __half* __restrict__ a, const __half* __restrict__ bres,
        __half* __restrict__ out)
{
    long i = (long)blockIdx.x * Dd + threadIdx.x;
    float v = __half2float(a[i]) + __half2float(bres[i]);
    float2 st = rowStats256(v);
    out[i] = __float2half_rn((v - st.x) * st.y);
}

// ---------------- kernel 5: x = LN(f2); total += x ----------------
__global__ void __launch_bounds__(256) ln_acc_kernel(
        const __half* __restrict__ f2, __half* __restrict__ x,
        float* __restrict__ out)
{
    long i = (long)blockIdx.x * Dd + threadIdx.x;
    float v = __half2float(f2[i]);
    float2 st = rowStats256(v);
    float y = (v - st.x) * st.y;
    x[i] = __float2half_rn(y);
    out[i] += y;
}

// ---------------- launch ----------------
extern "C" void kernel_launch(void* const* d_in, const int* in_sizes, int n_in,
                              void* d_out, int out_size)
{
    const int*   ids      = (const int*)  d_in[0];
    const float* item_emb = (const float*)d_in[1];
    const float* pos_emb  = (const float*)d_in[2];
    const float* Wq = (const float*)d_in[3];  const float* bq = (const float*)d_in[4];
    const float* Wk = (const float*)d_in[5];  const float* bk = (const float*)d_in[6];
    const float* Wv = (const float*)d_in[7];  const float* bv = (const float*)d_in[8];
    const float* Wo = (const float*)d_in[9];  const float* bo = (const float*)d_in[10];
    const float* W1 = (const float*)d_in[11]; const float* b1 = (const float*)d_in[12];
    const float* W2 = (const float*)d_in[13]; const float* b2 = (const float*)d_in[14];
    float* out = (float*)d_out;

    __half *x, *qkv, *ctx, *t, *h, *f1, *f2;
    __half *wqkvt, *wot, *w1t, *w2t;
    float  *bqkv;
    cudaGetSymbolAddress((void**)&x,     g_xh);
    cudaGetSymbolAddress((void**)&qkv,   g_qkv);
    cudaGetSymbolAddress((void**)&ctx,   g_ctx);
    cudaGetSymbolAddress((void**)&t,     g_t);
    cudaGetSymbolAddress((void**)&h,     g_hh);
    cudaGetSymbolAddress((void**)&f1,    g_f1);
    cudaGetSymbolAddress((void**)&f2,    g_f2);
    cudaGetSymbolAddress((void**)&wqkvt, g_wqkvt);
    cudaGetSymbolAddress((void**)&wot,   g_wot);
    cudaGetSymbolAddress((void**)&w1t,   g_w1t);
    cudaGetSymbolAddress((void**)&w2t,   g_w2t);
    cudaGetSymbolAddress((void**)&bqkv,  g_bqkv);

    cudaFuncSetAttribute(attn_f16_kernel,
                         cudaFuncAttributeMaxDynamicSharedMemorySize, ATTN_SMEM);

    // ---- one-launch weight conversion + bias packing ----
    wconv_all_kernel<<<Ll * 768 + Ll * 3, dim3(32, 8)>>>(
        Wq, Wk, Wv, Wo, W1, W2, bq, bk, bv, wqkvt, wot, w1t, w2t, bqkv);

    embed_ln_kernel<<<NROWS, 256>>>(ids, item_emb, pos_emb, x, out);

    dim3 gQKV(6, 512), gD(2, 512), gF(8, 512);

    for (int l = 0; l < Ll; l++) {
        gemm_f16_kernel<<<gQKV, 256>>>(x, wqkvt + (long)l*768*Dd, bqkv + l*768,
                                       qkv, 768, Dd, 0);

        attn_f16_kernel<<<Bb * Hh, 256, ATTN_SMEM>>>(qkv, ids, ctx);

        gemm_f16_kernel<<<gD, 256>>>(ctx, wot + (long)l*Dd*Dd, bo + l*Dd,
                                     t, Dd, Dd, 0);
        add_ln_kernel<<<NROWS, 256>>>(t, x, h);

        gemm_f16_kernel<<<gF, 256>>>(h, w1t + (long)l*FF*Dd, b1 + l*FF,
                                     f1, FF, Dd, 1);
        gemm_f16_kernel<<<gD, 256>>>(f1, w2t + (long)l*Dd*FF, b2 + l*Dd,
                                     f2, Dd, FF, 0);

        ln_acc_kernel<<<NROWS, 256>>>(f2, x, out);
    }
}

// round 12
// speedup vs baseline: 1.7636x; 1.2440x over previous
#include <cuda_runtime.h>
#include <cuda_fp16.h>
#include <math.h>
#include <stdint.h>

// ---------------- problem constants ----------------
#define Bb   256
#define Ss   256
#define Dd   256
#define Hh   4
#define DHh  64
#define Ll   2
#define FF   1024
#define NROWS (Bb*Ss)           // 65536

// ---------------- scratch (__device__ globals; no allocation) ----------------
__device__ __half g_xh [NROWS*Dd];
__device__ __half g_qkv[NROWS*768];
__device__ __half g_ctx[NROWS*Dd];
__device__ __half g_t  [NROWS*Dd];
__device__ __half g_hh [NROWS*Dd];
__device__ __half g_f1 [NROWS*FF];
__device__ __half g_f2 [NROWS*Dd];
// converted weights (transposed to [N][K], half)
__device__ __half g_wqkvt[Ll*768*Dd];
__device__ __half g_wot  [Ll*Dd*Dd];
__device__ __half g_w1t  [Ll*FF*Dd];
__device__ __half g_w2t  [Ll*Dd*FF];
__device__ float  g_bqkv [Ll*768];

// ---------------- helpers ----------------
__device__ __forceinline__ float gelu_exact(float x) {
    return 0.5f * x * (1.0f + erff(x * 0.70710678118654752440f));
}

__device__ __forceinline__ void mma_f16(float* d, const uint32_t* a, const uint32_t* b) {
    asm volatile(
        "mma.sync.aligned.m16n8k16.row.col.f32.f16.f16.f32 "
        "{%0,%1,%2,%3}, {%4,%5,%6,%7}, {%8,%9}, {%0,%1,%2,%3};"
        : "+f"(d[0]), "+f"(d[1]), "+f"(d[2]), "+f"(d[3])
        : "r"(a[0]), "r"(a[1]), "r"(a[2]), "r"(a[3]), "r"(b[0]), "r"(b[1]));
}

__device__ __forceinline__ uint32_t packh2(float lo, float hi) {
    __half2 h = __floats2half2_rn(lo, hi);
    return *reinterpret_cast<uint32_t*>(&h);
}

// warp-level mean+rstd over 8 values/lane (256-wide row in one warp)
__device__ __forceinline__ float2 warpStats256(const float* v) {
    float s = 0.0f, s2 = 0.0f;
    #pragma unroll
    for (int i = 0; i < 8; i++) { s += v[i]; s2 += v[i] * v[i]; }
    #pragma unroll
    for (int o = 16; o > 0; o >>= 1) {
        s  += __shfl_xor_sync(0xffffffffu, s,  o);
        s2 += __shfl_xor_sync(0xffffffffu, s2, o);
    }
    float mu  = s * (1.0f / 256.0f);
    float var = s2 * (1.0f / 256.0f) - mu * mu;
    return make_float2(mu, rsqrtf(var + 1e-5f));
}

// ---------------- merged weight conversion (ONE launch) ----------------------
__global__ void wconv_all_kernel(
        const float* __restrict__ Wq, const float* __restrict__ Wk,
        const float* __restrict__ Wv, const float* __restrict__ Wo,
        const float* __restrict__ W1, const float* __restrict__ W2,
        const float* __restrict__ bq, const float* __restrict__ bk,
        const float* __restrict__ bv,
        __half* __restrict__ wqkvt, __half* __restrict__ wot,
        __half* __restrict__ w1t,   __half* __restrict__ w2t,
        float* __restrict__ bqkv)
{
    int bid = blockIdx.x;
    int tx = threadIdx.x, ty = threadIdx.y;

    if (bid >= Ll * 768) {                    // bias packing
        int idx = bid - Ll * 768;
        int l = idx / 3, t = idx % 3;
        const float* s = (t == 0) ? bq : (t == 1) ? bk : bv;
        int i = ty * 32 + tx;
        bqkv[l * 768 + t * 256 + i] = s[l * 256 + i];
        return;
    }

    int l = bid / 768, r = bid % 768;
    const float* in; __half* out; int K, N, ti;
    if      (r < 64)  { in = Wq + (long)l*Dd*Dd; out = wqkvt + (long)l*768*Dd;            K = Dd; N = Dd; ti = r; }
    else if (r < 128) { in = Wk + (long)l*Dd*Dd; out = wqkvt + (long)l*768*Dd + 256*Dd;   K = Dd; N = Dd; ti = r - 64; }
    else if (r < 192) { in = Wv + (long)l*Dd*Dd; out = wqkvt + (long)l*768*Dd + 512*Dd;   K = Dd; N = Dd; ti = r - 128; }
    else if (r < 256) { in = Wo + (long)l*Dd*Dd; out = wot + (long)l*Dd*Dd;               K = Dd; N = Dd; ti = r - 192; }
    else if (r < 512) { in = W1 + (long)l*Dd*FF; out = w1t + (long)l*FF*Dd;               K = Dd; N = FF; ti = r - 256; }
    else              { in = W2 + (long)l*FF*Dd; out = w2t + (long)l*Dd*FF;               K = FF; N = Dd; ti = r - 512; }

    int ntx = N / 32;
    int n0 = (ti % ntx) * 32, k0 = (ti / ntx) * 32;

    __shared__ float t[32][33];
    #pragma unroll
    for (int i = 0; i < 32; i += 8)
        t[ty + i][tx] = in[(long)(k0 + ty + i) * N + n0 + tx];
    __syncthreads();
    #pragma unroll
    for (int i = 0; i < 32; i += 8)
        out[(long)(n0 + ty + i) * K + k0 + tx] = __float2half_rn(t[tx][ty + i]);
}

// ---------------- kernel 1: embedding + LN, warp-per-row ---------------------
__global__ void __launch_bounds__(256) embed_ln_kernel(
        const int* __restrict__ ids,
        const float* __restrict__ item_emb,
        const float* __restrict__ pos_emb,
        __half* __restrict__ x, float* __restrict__ out)
{
    int wid = threadIdx.x >> 5, lane = threadIdx.x & 31;
    int row = blockIdx.x * 8 + wid;
    int s   = row & (Ss - 1);
    int id  = ids[row];
    int c   = lane * 8;

    const float4* ie = (const float4*)(item_emb + (long)id * Dd + c);
    const float4* pe = (const float4*)(pos_emb + s * Dd + c);
    float4 a0 = ie[0], a1 = ie[1], p0 = pe[0], p1 = pe[1];
    float v[8] = {a0.x+p0.x, a0.y+p0.y, a0.z+p0.z, a0.w+p0.w,
                  a1.x+p1.x, a1.y+p1.y, a1.z+p1.z, a1.w+p1.w};
    float2 st = warpStats256(v);
    float y[8];
    #pragma unroll
    for (int i = 0; i < 8; i++) y[i] = (v[i] - st.x) * st.y;

    long o = (long)row * Dd + c;
    uint4 hx;
    hx.x = packh2(y[0], y[1]); hx.y = packh2(y[2], y[3]);
    hx.z = packh2(y[4], y[5]); hx.w = packh2(y[6], y[7]);
    *(uint4*)&x[o] = hx;
    *(float4*)&out[o]     = make_float4(y[0], y[1], y[2], y[3]);
    *(float4*)&out[o + 4] = make_float4(y[4], y[5], y[6], y[7]);
}

// ---------------- kernel 2: fp16 GEMM, explicit LDS frags, BK=64 -------------
// C(half)[M][N] = A(half)[M][K] @ Wt(half)[N][K]^T + bias(f32), optional GELU.
// BM=BN=128, BK=64, 256 threads (8 warps 4m x 2n), warp tile 32x64.
// Same verified fragment scheme as R7; BK=64 halves barrier count and doubles
// load-phase MLP. regs capped at 128 -> 2 blocks/SM co-residency guaranteed.
#define HS 72   // smem stride (halves); fragment word-banks (4g+tig) all-distinct

__global__ void __launch_bounds__(256, 2) gemm_f16_kernel(
        const __half* __restrict__ A, const __half* __restrict__ Wt,
        const float* __restrict__ bias, __half* __restrict__ C,
        int N, int K, int act)
{
    __shared__ __half As[128 * HS];
    __shared__ __half Bs[128 * HS];

    int tid  = threadIdx.x;
    int w    = tid >> 5, lane = tid & 31;
    int g    = lane >> 2, tig = lane & 3;
    int wm   = w >> 1,  wn = w & 1;
    int rowb = blockIdx.y * 128;
    int colb = blockIdx.x * 128;

    int sr = tid >> 1, sc = (tid & 1) * 32;
    const __half* Ag = A  + (long)(rowb + sr) * K + sc;
    const __half* Wg = Wt + (long)(colb + sr) * K + sc;

    float acc[2][8][4];
    #pragma unroll
    for (int mt = 0; mt < 2; mt++)
        #pragma unroll
        for (int nt = 0; nt < 8; nt++)
            #pragma unroll
            for (int r = 0; r < 4; r++) acc[mt][nt][r] = 0.0f;

    for (int kt = 0; kt < K; kt += 64) {
        __syncthreads();
        #pragma unroll
        for (int i = 0; i < 4; i++)
            *(uint4*)&As[sr * HS + sc + i * 8] = *(const uint4*)(Ag + kt + i * 8);
        #pragma unroll
        for (int i = 0; i < 4; i++)
            *(uint4*)&Bs[sr * HS + sc + i * 8] = *(const uint4*)(Wg + kt + i * 8);
        __syncthreads();

        #pragma unroll
        for (int ks = 0; ks < 4; ks++) {
            int k0 = ks * 16;
            uint32_t a[2][4], b[8][2];
            #pragma unroll
            for (int mt = 0; mt < 2; mt++) {
                int r0 = wm * 32 + mt * 16 + g;
                a[mt][0] = *(const uint32_t*)&As[ r0      * HS + k0 + 2 * tig];
                a[mt][1] = *(const uint32_t*)&As[(r0 + 8) * HS + k0 + 2 * tig];
                a[mt][2] = *(const uint32_t*)&As[ r0      * HS + k0 + 8 + 2 * tig];
                a[mt][3] = *(const uint32_t*)&As[(r0 + 8) * HS + k0 + 8 + 2 * tig];
            }
            #pragma unroll
            for (int nt = 0; nt < 8; nt++) {
                int n = wn * 64 + nt * 8 + g;
                b[nt][0] = *(const uint32_t*)&Bs[n * HS + k0 + 2 * tig];
                b[nt][1] = *(const uint32_t*)&Bs[n * HS + k0 + 8 + 2 * tig];
            }
            #pragma unroll
            for (int mt = 0; mt < 2; mt++)
                #pragma unroll
                for (int nt = 0; nt < 8; nt++)
                    mma_f16(acc[mt][nt], a[mt], b[nt]);
        }
    }

    #pragma unroll
    for (int mt = 0; mt < 2; mt++) {
        int row0 = rowb + wm * 32 + mt * 16 + g;
        #pragma unroll
        for (int nt = 0; nt < 8; nt++) {
            int col = colb + wn * 64 + nt * 8 + 2 * tig;
            float b0 = bias[col], b1 = bias[col + 1];
            float o0 = acc[mt][nt][0] + b0;
            float o1 = acc[mt][nt][1] + b1;
            float o2 = acc[mt][nt][2] + b0;
            float o3 = acc[mt][nt][3] + b1;
            if (act) { o0 = gelu_exact(o0); o1 = gelu_exact(o1);
                       o2 = gelu_exact(o2); o3 = gelu_exact(o3); }
            *(__half2*)&C[(long)row0 * N + col]       = __floats2half2_rn(o0, o1);
            *(__half2*)&C[(long)(row0 + 8) * N + col] = __floats2half2_rn(o2, o3);
        }
    }
}

// ---------------- kernel 3: fused fp16 attention (R7, unchanged) -------------
#define AS 72
#define VTS 264
#define ATTN_SMEM ((2 * Ss * AS + DHh * VTS) * 2 + Ss * 4)

__global__ void __launch_bounds__(256, 1) attn_f16_kernel(
        const __half* __restrict__ qkv, const int* __restrict__ ids,
        __half* __restrict__ ctx)
{
    extern __shared__ char smraw[];
    __half* sQ  = (__half*)smraw;            // 256 x 72
    __half* sK  = sQ + Ss * AS;              // 256 x 72
    __half* sVt = sK + Ss * AS;              // 64 x 264  (sVt[d][key])
    float* sBias = (float*)(sVt + DHh * VTS);

    int bh = blockIdx.x;
    int b = bh >> 2, h = bh & 3;
    int base = b * Ss, hoff = h * DHh;
    int tid = threadIdx.x;

    for (int idx = tid; idx < Ss * 8; idx += 256) {
        int r = idx >> 3, u = idx & 7;
        const __half* gp = qkv + (long)(base + r) * 768 + hoff + u * 8;
        *(uint4*)&sQ[r * AS + u * 8] = *(const uint4*)(gp);
        *(uint4*)&sK[r * AS + u * 8] = *(const uint4*)(gp + 256);
    }
    for (int idx = tid; idx < Ss * DHh; idx += 256) {
        int r = idx >> 6, d = idx & 63;
        sVt[d * VTS + r] = qkv[(long)(base + r) * 768 + 512 + hoff + d];
    }
    if (tid < Ss) sBias[tid] = (ids[base + tid] > 0) ? 0.0f : -10000.0f;
    __syncthreads();

    int w = tid >> 5, lane = tid & 31;
    int g = lane >> 2, tig = lane & 3;
    const float scale = 0.125f;

    for (int pass = 0; pass < 2; pass++) {
        int m0 = pass * 128 + w * 16;
        int r0 = m0 + g, r1 = m0 + 8 + g;

        uint32_t aS[4][4];
        #pragma unroll
        for (int kc = 0; kc < 4; kc++) {
            int c = kc * 16 + 2 * tig;
            aS[kc][0] = *(const uint32_t*)&sQ[ r0 * AS + c];
            aS[kc][1] = *(const uint32_t*)&sQ[ r1 * AS + c];
            aS[kc][2] = *(const uint32_t*)&sQ[ r0 * AS + c + 8];
            aS[kc][3] = *(const uint32_t*)&sQ[ r1 * AS + c + 8];
        }

        float acc[32][4];
        #pragma unroll
        for (int nt = 0; nt < 32; nt++)
            #pragma unroll
            for (int r = 0; r < 4; r++) acc[nt][r] = 0.0f;

        #pragma unroll
        for (int kc = 0; kc < 4; kc++) {
            int c = kc * 16 + 2 * tig;
            #pragma unroll
            for (int nt = 0; nt < 32; nt++) {
                int n = nt * 8 + g;
                uint32_t bb[2];
                bb[0] = *(const uint32_t*)&sK[n * AS + c];
                bb[1] = *(const uint32_t*)&sK[n * AS + c + 8];
                mma_f16(acc[nt], aS[kc], bb);
            }
        }

        float mx0 = -1e30f, mx1 = -1e30f;
        #pragma unroll
        for (int nt = 0; nt < 32; nt++) {
            int c0 = nt * 8 + 2 * tig, c1 = c0 + 1;
            float bp0 = sBias[c0], bp1 = sBias[c1];
            acc[nt][0] = acc[nt][0] * scale + ((c0 <= r0) ? bp0 : -10000.0f);
            acc[nt][1] = acc[nt][1] * scale + ((c1 <= r0) ? bp1 : -10000.0f);
            acc[nt][2] = acc[nt][2] * scale + ((c0 <= r1) ? bp0 : -10000.0f);
            acc[nt][3] = acc[nt][3] * scale + ((c1 <= r1) ? bp1 : -10000.0f);
            mx0 = fmaxf(mx0, fmaxf(acc[nt][0], acc[nt][1]));
            mx1 = fmaxf(mx1, fmaxf(acc[nt][2], acc[nt][3]));
        }
        mx0 = fmaxf(mx0, __shfl_xor_sync(0xffffffffu, mx0, 1));
        mx0 = fmaxf(mx0, __shfl_xor_sync(0xffffffffu, mx0, 2));
        mx1 = fmaxf(mx1, __shfl_xor_sync(0xffffffffu, mx1, 1));
        mx1 = fmaxf(mx1, __shfl_xor_sync(0xffffffffu, mx1, 2));

        float s0 = 0.0f, s1 = 0.0f;
        #pragma unroll
        for (int nt = 0; nt < 32; nt++) {
            acc[nt][0] = __expf(acc[nt][0] - mx0);
            acc[nt][1] = __expf(acc[nt][1] - mx0);
            acc[nt][2] = __expf(acc[nt][2] - mx1);
            acc[nt][3] = __expf(acc[nt][3] - mx1);
            s0 += acc[nt][0] + acc[nt][1];
            s1 += acc[nt][2] + acc[nt][3];
        }
        s0 += __shfl_xor_sync(0xffffffffu, s0, 1);
        s0 += __shfl_xor_sync(0xffffffffu, s0, 2);
        s1 += __shfl_xor_sync(0xffffffffu, s1, 1);
        s1 += __shfl_xor_sync(0xffffffffu, s1, 2);
        float i0 = 1.0f / s0, i1 = 1.0f / s1;

        float acc2[8][4];
        #pragma unroll
        for (int nt = 0; nt < 8; nt++)
            #pragma unroll
            for (int r = 0; r < 4; r++) acc2[nt][r] = 0.0f;

        #pragma unroll
        for (int kc = 0; kc < 16; kc++) {
            uint32_t a[4];
            a[0] = packh2(acc[2*kc][0]   * i0, acc[2*kc][1]   * i0);
            a[1] = packh2(acc[2*kc][2]   * i1, acc[2*kc][3]   * i1);
            a[2] = packh2(acc[2*kc+1][0] * i0, acc[2*kc+1][1] * i0);
            a[3] = packh2(acc[2*kc+1][2] * i1, acc[2*kc+1][3] * i1);
            int c = kc * 16 + 2 * tig;
            #pragma unroll
            for (int nt = 0; nt < 8; nt++) {
                int d = nt * 8 + g;
                uint32_t bb[2];
                bb[0] = *(const uint32_t*)&sVt[d * VTS + c];
                bb[1] = *(const uint32_t*)&sVt[d * VTS + c + 8];
                mma_f16(acc2[nt], a, bb);
            }
        }

        long o0 = (long)(base + r0) * Dd + hoff;
        long o1 = (long)(base + r1) * Dd + hoff;
        #pragma unroll
        for (int nt = 0; nt < 8; nt++) {
            int d = nt * 8 + 2 * tig;
            *(__half2*)&ctx[o0 + d] = __floats2half2_rn(acc2[nt][0], acc2[nt][1]);
            *(__half2*)&ctx[o1 + d] = __floats2half2_rn(acc2[nt][2], acc2[nt][3]);
        }
    }
}

// ---------------- kernel 4: h = LN(t + x), warp-per-row ----------------------
__global__ void __launch_bounds__(256) add_ln_kernel(
        const __half* __restrict__ a, const __half* __restrict__ bres,
        __half* __restrict__ out)
{
    int wid = threadIdx.x >> 5, lane = threadIdx.x & 31;
    long o = (long)(blockIdx.x * 8 + wid) * Dd + lane * 8;

    uint4 ha = *(const uint4*)&a[o];
    uint4 hb = *(const uint4*)&bres[o];
    const __half2* pa = (const __half2*)&ha;
    const __half2* pb = (const __half2*)&hb;
    float v[8];
    #pragma unroll
    for (int i = 0; i < 4; i++) {
        float2 fa = __half22float2(pa[i]);
        float2 fb = __half22float2(pb[i]);
        v[2*i]   = fa.x + fb.x;
        v[2*i+1] = fa.y + fb.y;
    }
    float2 st = warpStats256(v);
    uint4 ho;
    ho.x = packh2((v[0]-st.x)*st.y, (v[1]-st.x)*st.y);
    ho.y = packh2((v[2]-st.x)*st.y, (v[3]-st.x)*st.y);
    ho.z = packh2((v[4]-st.x)*st.y, (v[5]-st.x)*st.y);
    ho.w = packh2((v[6]-st.x)*st.y, (v[7]-st.x)*st.y);
    *(uint4*)&out[o] = ho;
}

// ---------------- kernel 5: x = LN(f2); total += x, warp-per-row -------------
__global__ void __launch_bounds__(256) ln_acc_kernel(
        const __half* __restrict__ f2, __half* __restrict__ x,
        float* __restrict__ out)
{
    int wid = threadIdx.x >> 5, lane = threadIdx.x & 31;
    long o = (long)(blockIdx.x * 8 + wid) * Dd + lane * 8;

    uint4 hf = *(const uint4*)&f2[o];
    const __half2* pf = (const __half2*)&hf;
    float v[8];
    #pragma unroll
    for (int i = 0; i < 4; i++) {
        float2 ff = __half22float2(pf[i]);
        v[2*i]   = ff.x;
        v[2*i+1] = ff.y;
    }
    float2 st = warpStats256(v);
    float y[8];
    #pragma unroll
    for (int i = 0; i < 8; i++) y[i] = (v[i] - st.x) * st.y;

    uint4 hx;
    hx.x = packh2(y[0], y[1]); hx.y = packh2(y[2], y[3]);
    hx.z = packh2(y[4], y[5]); hx.w = packh2(y[6], y[7]);
    *(uint4*)&x[o] = hx;

    float4 t0 = *(float4*)&out[o];
    float4 t1 = *(float4*)&out[o + 4];
    t0.x += y[0]; t0.y += y[1]; t0.z += y[2]; t0.w += y[3];
    t1.x += y[4]; t1.y += y[5]; t1.z += y[6]; t1.w += y[7];
    *(float4*)&out[o]     = t0;
    *(float4*)&out[o + 4] = t1;
}

// ---------------- launch ----------------
extern "C" void kernel_launch(void* const* d_in, const int* in_sizes, int n_in,
                              void* d_out, int out_size)
{
    const int*   ids      = (const int*)  d_in[0];
    const float* item_emb = (const float*)d_in[1];
    const float* pos_emb  = (const float*)d_in[2];
    const float* Wq = (const float*)d_in[3];  const float* bq = (const float*)d_in[4];
    const float* Wk = (const float*)d_in[5];  const float* bk = (const float*)d_in[6];
    const float* Wv = (const float*)d_in[7];  const float* bv = (const float*)d_in[8];
    const float* Wo = (const float*)d_in[9];  const float* bo = (const float*)d_in[10];
    const float* W1 = (const float*)d_in[11]; const float* b1 = (const float*)d_in[12];
    const float* W2 = (const float*)d_in[13]; const float* b2 = (const float*)d_in[14];
    float* out = (float*)d_out;

    __half *x, *qkv, *ctx, *t, *h, *f1, *f2;
    __half *wqkvt, *wot, *w1t, *w2t;
    float  *bqkv;
    cudaGetSymbolAddress((void**)&x,     g_xh);
    cudaGetSymbolAddress((void**)&qkv,   g_qkv);
    cudaGetSymbolAddress((void**)&ctx,   g_ctx);
    cudaGetSymbolAddress((void**)&t,     g_t);
    cudaGetSymbolAddress((void**)&h,     g_hh);
    cudaGetSymbolAddress((void**)&f1,    g_f1);
    cudaGetSymbolAddress((void**)&f2,    g_f2);
    cudaGetSymbolAddress((void**)&wqkvt, g_wqkvt);
    cudaGetSymbolAddress((void**)&wot,   g_wot);
    cudaGetSymbolAddress((void**)&w1t,   g_w1t);
    cudaGetSymbolAddress((void**)&w2t,   g_w2t);
    cudaGetSymbolAddress((void**)&bqkv,  g_bqkv);

    cudaFuncSetAttribute(attn_f16_kernel,
                         cudaFuncAttributeMaxDynamicSharedMemorySize, ATTN_SMEM);

    // ---- one-launch weight conversion + bias packing ----
    wconv_all_kernel<<<Ll * 768 + Ll * 3, dim3(32, 8)>>>(
        Wq, Wk, Wv, Wo, W1, W2, bq, bk, bv, wqkvt, wot, w1t, w2t, bqkv);

    embed_ln_kernel<<<NROWS / 8, 256>>>(ids, item_emb, pos_emb, x, out);

    dim3 gQKV(6, 512), gD(2, 512), gF(8, 512);

    for (int l = 0; l < Ll; l++) {
        gemm_f16_kernel<<<gQKV, 256>>>(x, wqkvt + (long)l*768*Dd, bqkv + l*768,
                                       qkv, 768, Dd, 0);

        attn_f16_kernel<<<Bb * Hh, 256, ATTN_SMEM>>>(qkv, ids, ctx);

        gemm_f16_kernel<<<gD, 256>>>(ctx, wot + (long)l*Dd*Dd, bo + l*Dd,
                                     t, Dd, Dd, 0);
        add_ln_kernel<<<NROWS / 8, 256>>>(t, x, h);

        gemm_f16_kernel<<<gF, 256>>>(h, w1t + (long)l*FF*Dd, b1 + l*FF,
                                     f1, FF, Dd, 1);
        gemm_f16_kernel<<<gD, 256>>>(f1, w2t + (long)l*Dd*FF, b2 + l*Dd,
                                     f2, Dd, FF, 0);

        ln_acc_kernel<<<NROWS / 8, 256>>>(f2, x, out);
    }
}

// round 13
// speedup vs baseline: 1.9466x; 1.1038x over previous
#include <cuda_runtime.h>
#include <cuda_fp16.h>
#include <math.h>
#include <stdint.h>

// ---------------- problem constants ----------------
#define Bb   256
#define Ss   256
#define Dd   256
#define Hh   4
#define DHh  64
#define Ll   2
#define FF   1024
#define NROWS (Bb*Ss)           // 65536

// ---------------- scratch (__device__ globals; no allocation) ----------------
__device__ __half g_xh [NROWS*Dd];
__device__ __half g_qkv[NROWS*768];
__device__ __half g_ctx[NROWS*Dd];
__device__ __half g_t  [NROWS*Dd];
__device__ __half g_hh [NROWS*Dd];
__device__ __half g_f1 [NROWS*FF];
__device__ __half g_f2 [NROWS*Dd];
// converted weights (transposed to [N][K], half)
__device__ __half g_wqkvt[Ll*768*Dd];
__device__ __half g_wot  [Ll*Dd*Dd];
__device__ __half g_w1t  [Ll*FF*Dd];
__device__ __half g_w2t  [Ll*Dd*FF];
__device__ float  g_bqkv [Ll*768];

// ---------------- helpers ----------------
__device__ __forceinline__ float gelu_exact(float x) {
    return 0.5f * x * (1.0f + erff(x * 0.70710678118654752440f));
}

__device__ __forceinline__ void mma_f16(float* d, const uint32_t* a, const uint32_t* b) {
    asm volatile(
        "mma.sync.aligned.m16n8k16.row.col.f32.f16.f16.f32 "
        "{%0,%1,%2,%3}, {%4,%5,%6,%7}, {%8,%9}, {%0,%1,%2,%3};"
        : "+f"(d[0]), "+f"(d[1]), "+f"(d[2]), "+f"(d[3])
        : "r"(a[0]), "r"(a[1]), "r"(a[2]), "r"(a[3]), "r"(b[0]), "r"(b[1]));
}

__device__ __forceinline__ uint32_t packh2(float lo, float hi) {
    __half2 h = __floats2half2_rn(lo, hi);
    return *reinterpret_cast<uint32_t*>(&h);
}

// warp-level mean+rstd over 8 values/lane (256-wide row in one warp)
__device__ __forceinline__ float2 warpStats256(const float* v) {
    float s = 0.0f, s2 = 0.0f;
    #pragma unroll
    for (int i = 0; i < 8; i++) { s += v[i]; s2 += v[i] * v[i]; }
    #pragma unroll
    for (int o = 16; o > 0; o >>= 1) {
        s  += __shfl_xor_sync(0xffffffffu, s,  o);
        s2 += __shfl_xor_sync(0xffffffffu, s2, o);
    }
    float mu  = s * (1.0f / 256.0f);
    float var = s2 * (1.0f / 256.0f) - mu * mu;
    return make_float2(mu, rsqrtf(var + 1e-5f));
}

// ---------------- merged weight conversion (ONE launch) ----------------------
__global__ void wconv_all_kernel(
        const float* __restrict__ Wq, const float* __restrict__ Wk,
        const float* __restrict__ Wv, const float* __restrict__ Wo,
        const float* __restrict__ W1, const float* __restrict__ W2,
        const float* __restrict__ bq, const float* __restrict__ bk,
        const float* __restrict__ bv,
        __half* __restrict__ wqkvt, __half* __restrict__ wot,
        __half* __restrict__ w1t,   __half* __restrict__ w2t,
        float* __restrict__ bqkv)
{
    int bid = blockIdx.x;
    int tx = threadIdx.x, ty = threadIdx.y;

    if (bid >= Ll * 768) {                    // bias packing
        int idx = bid - Ll * 768;
        int l = idx / 3, t = idx % 3;
        const float* s = (t == 0) ? bq : (t == 1) ? bk : bv;
        int i = ty * 32 + tx;
        bqkv[l * 768 + t * 256 + i] = s[l * 256 + i];
        return;
    }

    int l = bid / 768, r = bid % 768;
    const float* in; __half* out; int K, N, ti;
    if      (r < 64)  { in = Wq + (long)l*Dd*Dd; out = wqkvt + (long)l*768*Dd;            K = Dd; N = Dd; ti = r; }
    else if (r < 128) { in = Wk + (long)l*Dd*Dd; out = wqkvt + (long)l*768*Dd + 256*Dd;   K = Dd; N = Dd; ti = r - 64; }
    else if (r < 192) { in = Wv + (long)l*Dd*Dd; out = wqkvt + (long)l*768*Dd + 512*Dd;   K = Dd; N = Dd; ti = r - 128; }
    else if (r < 256) { in = Wo + (long)l*Dd*Dd; out = wot + (long)l*Dd*Dd;               K = Dd; N = Dd; ti = r - 192; }
    else if (r < 512) { in = W1 + (long)l*Dd*FF; out = w1t + (long)l*FF*Dd;               K = Dd; N = FF; ti = r - 256; }
    else              { in = W2 + (long)l*FF*Dd; out = w2t + (long)l*Dd*FF;               K = FF; N = Dd; ti = r - 512; }

    int ntx = N / 32;
    int n0 = (ti % ntx) * 32, k0 = (ti / ntx) * 32;

    __shared__ float t[32][33];
    #pragma unroll
    for (int i = 0; i < 32; i += 8)
        t[ty + i][tx] = in[(long)(k0 + ty + i) * N + n0 + tx];
    __syncthreads();
    #pragma unroll
    for (int i = 0; i < 32; i += 8)
        out[(long)(n0 + ty + i) * K + k0 + tx] = __float2half_rn(t[tx][ty + i]);
}

// ---------------- kernel 1: embedding + LN, warp-per-row ---------------------
__global__ void __launch_bounds__(256) embed_ln_kernel(
        const int* __restrict__ ids,
        const float* __restrict__ item_emb,
        const float* __restrict__ pos_emb,
        __half* __restrict__ x, float* __restrict__ out)
{
    int wid = threadIdx.x >> 5, lane = threadIdx.x & 31;
    int row = blockIdx.x * 8 + wid;
    int s   = row & (Ss - 1);
    int id  = ids[row];
    int c   = lane * 8;

    const float4* ie = (const float4*)(item_emb + (long)id * Dd + c);
    const float4* pe = (const float4*)(pos_emb + s * Dd + c);
    float4 a0 = ie[0], a1 = ie[1], p0 = pe[0], p1 = pe[1];
    float v[8] = {a0.x+p0.x, a0.y+p0.y, a0.z+p0.z, a0.w+p0.w,
                  a1.x+p1.x, a1.y+p1.y, a1.z+p1.z, a1.w+p1.w};
    float2 st = warpStats256(v);
    float y[8];
    #pragma unroll
    for (int i = 0; i < 8; i++) y[i] = (v[i] - st.x) * st.y;

    long o = (long)row * Dd + c;
    uint4 hx;
    hx.x = packh2(y[0], y[1]); hx.y = packh2(y[2], y[3]);
    hx.z = packh2(y[4], y[5]); hx.w = packh2(y[6], y[7]);
    *(uint4*)&x[o] = hx;
    *(float4*)&out[o]     = make_float4(y[0], y[1], y[2], y[3]);
    *(float4*)&out[o + 4] = make_float4(y[4], y[5], y[6], y[7]);
}

// ---------------- kernel 2: fp16 GEMM, explicit LDS frags, BK=64 (R12) -------
#define HS 72

__global__ void __launch_bounds__(256, 2) gemm_f16_kernel(
        const __half* __restrict__ A, const __half* __restrict__ Wt,
        const float* __restrict__ bias, __half* __restrict__ C,
        int N, int K, int act)
{
    __shared__ __half As[128 * HS];
    __shared__ __half Bs[128 * HS];

    int tid  = threadIdx.x;
    int w    = tid >> 5, lane = tid & 31;
    int g    = lane >> 2, tig = lane & 3;
    int wm   = w >> 1,  wn = w & 1;
    int rowb = blockIdx.y * 128;
    int colb = blockIdx.x * 128;

    int sr = tid >> 1, sc = (tid & 1) * 32;
    const __half* Ag = A  + (long)(rowb + sr) * K + sc;
    const __half* Wg = Wt + (long)(colb + sr) * K + sc;

    float acc[2][8][4];
    #pragma unroll
    for (int mt = 0; mt < 2; mt++)
        #pragma unroll
        for (int nt = 0; nt < 8; nt++)
            #pragma unroll
            for (int r = 0; r < 4; r++) acc[mt][nt][r] = 0.0f;

    for (int kt = 0; kt < K; kt += 64) {
        __syncthreads();
        #pragma unroll
        for (int i = 0; i < 4; i++)
            *(uint4*)&As[sr * HS + sc + i * 8] = *(const uint4*)(Ag + kt + i * 8);
        #pragma unroll
        for (int i = 0; i < 4; i++)
            *(uint4*)&Bs[sr * HS + sc + i * 8] = *(const uint4*)(Wg + kt + i * 8);
        __syncthreads();

        #pragma unroll
        for (int ks = 0; ks < 4; ks++) {
            int k0 = ks * 16;
            uint32_t a[2][4], b[8][2];
            #pragma unroll
            for (int mt = 0; mt < 2; mt++) {
                int r0 = wm * 32 + mt * 16 + g;
                a[mt][0] = *(const uint32_t*)&As[ r0      * HS + k0 + 2 * tig];
                a[mt][1] = *(const uint32_t*)&As[(r0 + 8) * HS + k0 + 2 * tig];
                a[mt][2] = *(const uint32_t*)&As[ r0      * HS + k0 + 8 + 2 * tig];
                a[mt][3] = *(const uint32_t*)&As[(r0 + 8) * HS + k0 + 8 + 2 * tig];
            }
            #pragma unroll
            for (int nt = 0; nt < 8; nt++) {
                int n = wn * 64 + nt * 8 + g;
                b[nt][0] = *(const uint32_t*)&Bs[n * HS + k0 + 2 * tig];
                b[nt][1] = *(const uint32_t*)&Bs[n * HS + k0 + 8 + 2 * tig];
            }
            #pragma unroll
            for (int mt = 0; mt < 2; mt++)
                #pragma unroll
                for (int nt = 0; nt < 8; nt++)
                    mma_f16(acc[mt][nt], a[mt], b[nt]);
        }
    }

    #pragma unroll
    for (int mt = 0; mt < 2; mt++) {
        int row0 = rowb + wm * 32 + mt * 16 + g;
        #pragma unroll
        for (int nt = 0; nt < 8; nt++) {
            int col = colb + wn * 64 + nt * 8 + 2 * tig;
            float b0 = bias[col], b1 = bias[col + 1];
            float o0 = acc[mt][nt][0] + b0;
            float o1 = acc[mt][nt][1] + b1;
            float o2 = acc[mt][nt][2] + b0;
            float o3 = acc[mt][nt][3] + b1;
            if (act) { o0 = gelu_exact(o0); o1 = gelu_exact(o1);
                       o2 = gelu_exact(o2); o3 = gelu_exact(o3); }
            *(__half2*)&C[(long)row0 * N + col]       = __floats2half2_rn(o0, o1);
            *(__half2*)&C[(long)(row0 + 8) * N + col] = __floats2half2_rn(o2, o3);
        }
    }
}

// ---------------- kernel 3: fused fp16 attention, causal-chunked flash -------
// One block per (b,h); 256 threads (8 warps); warp = 16 q-rows per pass.
// Keys processed in 64-wide chunks with online softmax; chunks fully above
// the causal diagonal are skipped entirely (avg 2.5/4 chunks).
#define AS 72
#define VTS 264
#define ATTN_SMEM ((2 * Ss * AS + DHh * VTS) * 2 + Ss * 4)

__global__ void __launch_bounds__(256, 2) attn_f16_kernel(
        const __half* __restrict__ qkv, const int* __restrict__ ids,
        __half* __restrict__ ctx)
{
    extern __shared__ char smraw[];
    __half* sQ  = (__half*)smraw;            // 256 x 72
    __half* sK  = sQ + Ss * AS;              // 256 x 72
    __half* sVt = sK + Ss * AS;              // 64 x 264  (sVt[d][key])
    float* sBias = (float*)(sVt + DHh * VTS);

    int bh = blockIdx.x;
    int b = bh >> 2, h = bh & 3;
    int base = b * Ss, hoff = h * DHh;
    int tid = threadIdx.x;

    for (int idx = tid; idx < Ss * 8; idx += 256) {
        int r = idx >> 3, u = idx & 7;
        const __half* gp = qkv + (long)(base + r) * 768 + hoff + u * 8;
        *(uint4*)&sQ[r * AS + u * 8] = *(const uint4*)(gp);
        *(uint4*)&sK[r * AS + u * 8] = *(const uint4*)(gp + 256);
    }
    for (int idx = tid; idx < Ss * DHh; idx += 256) {
        int r = idx >> 6, d = idx & 63;
        sVt[d * VTS + r] = qkv[(long)(base + r) * 768 + 512 + hoff + d];
    }
    if (tid < Ss) sBias[tid] = (ids[base + tid] > 0) ? 0.0f : -10000.0f;
    __syncthreads();

    int w = tid >> 5, lane = tid & 31;
    int g = lane >> 2, tig = lane & 3;
    const float scale = 0.125f;

    for (int pass = 0; pass < 2; pass++) {
        int m0 = pass * 128 + w * 16;
        int r0 = m0 + g, r1 = m0 + 8 + g;

        // Q fragments (4 ksteps of 16 over d=64)
        uint32_t aS[4][4];
        #pragma unroll
        for (int kc = 0; kc < 4; kc++) {
            int c = kc * 16 + 2 * tig;
            aS[kc][0] = *(const uint32_t*)&sQ[ r0 * AS + c];
            aS[kc][1] = *(const uint32_t*)&sQ[ r1 * AS + c];
            aS[kc][2] = *(const uint32_t*)&sQ[ r0 * AS + c + 8];
            aS[kc][3] = *(const uint32_t*)&sQ[ r1 * AS + c + 8];
        }

        float acc2[8][4];
        #pragma unroll
        for (int nt = 0; nt < 8; nt++)
            #pragma unroll
            for (int r = 0; r < 4; r++) acc2[nt][r] = 0.0f;

        float mrun0 = -1e30f, mrun1 = -1e30f;
        float sum0 = 0.0f, sum1 = 0.0f;       // lane-partial (reduced at end)

        int nChunks = ((m0 + 15) >> 6) + 1;   // causal: skip all-masked chunks

        for (int ch = 0; ch < nChunks; ch++) {
            int key0 = ch * 64;

            // ---- S chunk = Q K^T over keys [key0, key0+64) ----
            float s[8][4];
            #pragma unroll
            for (int nt = 0; nt < 8; nt++)
                #pragma unroll
                for (int r = 0; r < 4; r++) s[nt][r] = 0.0f;

            #pragma unroll
            for (int kc = 0; kc < 4; kc++) {
                int c = kc * 16 + 2 * tig;
                #pragma unroll
                for (int nt = 0; nt < 8; nt++) {
                    int n = key0 + nt * 8 + g;
                    uint32_t bb[2];
                    bb[0] = *(const uint32_t*)&sK[n * AS + c];
                    bb[1] = *(const uint32_t*)&sK[n * AS + c + 8];
                    mma_f16(s[nt], aS[kc], bb);
                }
            }

            // ---- bias + causal mask + chunk max ----
            float cm0 = -1e30f, cm1 = -1e30f;
            #pragma unroll
            for (int nt = 0; nt < 8; nt++) {
                int c0 = key0 + nt * 8 + 2 * tig, c1 = c0 + 1;
                float bp0 = sBias[c0], bp1 = sBias[c1];
                s[nt][0] = s[nt][0] * scale + ((c0 <= r0) ? bp0 : -10000.0f);
                s[nt][1] = s[nt][1] * scale + ((c1 <= r0) ? bp1 : -10000.0f);
                s[nt][2] = s[nt][2] * scale + ((c0 <= r1) ? bp0 : -10000.0f);
                s[nt][3] = s[nt][3] * scale + ((c1 <= r1) ? bp1 : -10000.0f);
                cm0 = fmaxf(cm0, fmaxf(s[nt][0], s[nt][1]));
                cm1 = fmaxf(cm1, fmaxf(s[nt][2], s[nt][3]));
            }
            cm0 = fmaxf(cm0, __shfl_xor_sync(0xffffffffu, cm0, 1));
            cm0 = fmaxf(cm0, __shfl_xor_sync(0xffffffffu, cm0, 2));
            cm1 = fmaxf(cm1, __shfl_xor_sync(0xffffffffu, cm1, 1));
            cm1 = fmaxf(cm1, __shfl_xor_sync(0xffffffffu, cm1, 2));

            // ---- online softmax rescale ----
            float mn0 = fmaxf(mrun0, cm0), mn1 = fmaxf(mrun1, cm1);
            float rs0 = __expf(mrun0 - mn0), rs1 = __expf(mrun1 - mn1);
            sum0 *= rs0; sum1 *= rs1;
            #pragma unroll
            for (int nt = 0; nt < 8; nt++) {
                acc2[nt][0] *= rs0; acc2[nt][1] *= rs0;
                acc2[nt][2] *= rs1; acc2[nt][3] *= rs1;
            }
            mrun0 = mn0; mrun1 = mn1;

            #pragma unroll
            for (int nt = 0; nt < 8; nt++) {
                s[nt][0] = __expf(s[nt][0] - mn0);
                s[nt][1] = __expf(s[nt][1] - mn0);
                s[nt][2] = __expf(s[nt][2] - mn1);
                s[nt][3] = __expf(s[nt][3] - mn1);
                sum0 += s[nt][0] + s[nt][1];
                sum1 += s[nt][2] + s[nt][3];
            }

            // ---- P @ V for this chunk (C-frag == A-frag, keys = k dim) ----
            #pragma unroll
            for (int kc = 0; kc < 4; kc++) {
                uint32_t a[4];
                a[0] = packh2(s[2*kc][0],   s[2*kc][1]);
                a[1] = packh2(s[2*kc][2],   s[2*kc][3]);
                a[2] = packh2(s[2*kc+1][0], s[2*kc+1][1]);
                a[3] = packh2(s[2*kc+1][2], s[2*kc+1][3]);
                int c = key0 + kc * 16 + 2 * tig;
                #pragma unroll
                for (int nt = 0; nt < 8; nt++) {
                    int d = nt * 8 + g;
                    uint32_t bb[2];
                    bb[0] = *(const uint32_t*)&sVt[d * VTS + c];
                    bb[1] = *(const uint32_t*)&sVt[d * VTS + c + 8];
                    mma_f16(acc2[nt], a, bb);
                }
            }
        }

        // ---- final sum reduction + normalize + store ----
        sum0 += __shfl_xor_sync(0xffffffffu, sum0, 1);
        sum0 += __shfl_xor_sync(0xffffffffu, sum0, 2);
        sum1 += __shfl_xor_sync(0xffffffffu, sum1, 1);
        sum1 += __shfl_xor_sync(0xffffffffu, sum1, 2);
        float i0 = 1.0f / sum0, i1 = 1.0f / sum1;

        long o0 = (long)(base + r0) * Dd + hoff;
        long o1 = (long)(base + r1) * Dd + hoff;
        #pragma unroll
        for (int nt = 0; nt < 8; nt++) {
            int d = nt * 8 + 2 * tig;
            *(__half2*)&ctx[o0 + d] = __floats2half2_rn(acc2[nt][0] * i0, acc2[nt][1] * i0);
            *(__half2*)&ctx[o1 + d] = __floats2half2_rn(acc2[nt][2] * i1, acc2[nt][3] * i1);
        }
    }
}

// ---------------- kernel 4: h = LN(t + x), warp-per-row ----------------------
__global__ void __launch_bounds__(256) add_ln_kernel(
        const __half* __restrict__ a, const __half* __restrict__ bres,
        __half* __restrict__ out)
{
    int wid = threadIdx.x >> 5, lane = threadIdx.x & 31;
    long o = (long)(blockIdx.x * 8 + wid) * Dd + lane * 8;

    uint4 ha = *(const uint4*)&a[o];
    uint4 hb = *(const uint4*)&bres[o];
    const __half2* pa = (const __half2*)&ha;
    const __half2* pb = (const __half2*)&hb;
    float v[8];
    #pragma unroll
    for (int i = 0; i < 4; i++) {
        float2 fa = __half22float2(pa[i]);
        float2 fb = __half22float2(pb[i]);
        v[2*i]   = fa.x + fb.x;
        v[2*i+1] = fa.y + fb.y;
    }
    float2 st = warpStats256(v);
    uint4 ho;
    ho.x = packh2((v[0]-st.x)*st.y, (v[1]-st.x)*st.y);
    ho.y = packh2((v[2]-st.x)*st.y, (v[3]-st.x)*st.y);
    ho.z = packh2((v[4]-st.x)*st.y, (v[5]-st.x)*st.y);
    ho.w = packh2((v[6]-st.x)*st.y, (v[7]-st.x)*st.y);
    *(uint4*)&out[o] = ho;
}

// ---------------- kernel 5: x = LN(f2); total += x, warp-per-row -------------
__global__ void __launch_bounds__(256) ln_acc_kernel(
        const __half* __restrict__ f2, __half* __restrict__ x,
        float* __restrict__ out)
{
    int wid = threadIdx.x >> 5, lane = threadIdx.x & 31;
    long o = (long)(blockIdx.x * 8 + wid) * Dd + lane * 8;

    uint4 hf = *(const uint4*)&f2[o];
    const __half2* pf = (const __half2*)&hf;
    float v[8];
    #pragma unroll
    for (int i = 0; i < 4; i++) {
        float2 ff = __half22float2(pf[i]);
        v[2*i]   = ff.x;
        v[2*i+1] = ff.y;
    }
    float2 st = warpStats256(v);
    float y[8];
    #pragma unroll
    for (int i = 0; i < 8; i++) y[i] = (v[i] - st.x) * st.y;

    uint4 hx;
    hx.x = packh2(y[0], y[1]); hx.y = packh2(y[2], y[3]);
    hx.z = packh2(y[4], y[5]); hx.w = packh2(y[6], y[7]);
    *(uint4*)&x[o] = hx;

    float4 t0 = *(float4*)&out[o];
    float4 t1 = *(float4*)&out[o + 4];
    t0.x += y[0]; t0.y += y[1]; t0.z += y[2]; t0.w += y[3];
    t1.x += y[4]; t1.y += y[5]; t1.z += y[6]; t1.w += y[7];
    *(float4*)&out[o]     = t0;
    *(float4*)&out[o + 4] = t1;
}

// ---------------- launch ----------------
extern "C" void kernel_launch(void* const* d_in, const int* in_sizes, int n_in,
                              void* d_out, int out_size)
{
    const int*   ids      = (const int*)  d_in[0];
    const float* item_emb = (const float*)d_in[1];
    const float* pos_emb  = (const float*)d_in[2];
    const float* Wq = (const float*)d_in[3];  const float* bq = (const float*)d_in[4];
    const float* Wk = (const float*)d_in[5];  const float* bk = (const float*)d_in[6];
    const float* Wv = (const float*)d_in[7];  const float* bv = (const float*)d_in[8];
    const float* Wo = (const float*)d_in[9];  const float* bo = (const float*)d_in[10];
    const float* W1 = (const float*)d_in[11]; const float* b1 = (const float*)d_in[12];
    const float* W2 = (const float*)d_in[13]; const float* b2 = (const float*)d_in[14];
    float* out = (float*)d_out;

    __half *x, *qkv, *ctx, *t, *h, *f1, *f2;
    __half *wqkvt, *wot, *w1t, *w2t;
    float  *bqkv;
    cudaGetSymbolAddress((void**)&x,     g_xh);
    cudaGetSymbolAddress((void**)&qkv,   g_qkv);
    cudaGetSymbolAddress((void**)&ctx,   g_ctx);
    cudaGetSymbolAddress((void**)&t,     g_t);
    cudaGetSymbolAddress((void**)&h,     g_hh);
    cudaGetSymbolAddress((void**)&f1,    g_f1);
    cudaGetSymbolAddress((void**)&f2,    g_f2);
    cudaGetSymbolAddress((void**)&wqkvt, g_wqkvt);
    cudaGetSymbolAddress((void**)&wot,   g_wot);
    cudaGetSymbolAddress((void**)&w1t,   g_w1t);
    cudaGetSymbolAddress((void**)&w2t,   g_w2t);
    cudaGetSymbolAddress((void**)&bqkv,  g_bqkv);

    cudaFuncSetAttribute(attn_f16_kernel,
                         cudaFuncAttributeMaxDynamicSharedMemorySize, ATTN_SMEM);

    // ---- one-launch weight conversion + bias packing ----
    wconv_all_kernel<<<Ll * 768 + Ll * 3, dim3(32, 8)>>>(
        Wq, Wk, Wv, Wo, W1, W2, bq, bk, bv, wqkvt, wot, w1t, w2t, bqkv);

    embed_ln_kernel<<<NROWS / 8, 256>>>(ids, item_emb, pos_emb, x, out);

    dim3 gQKV(6, 512), gD(2, 512), gF(8, 512);

    for (int l = 0; l < Ll; l++) {
        gemm_f16_kernel<<<gQKV, 256>>>(x, wqkvt + (long)l*768*Dd, bqkv + l*768,
                                       qkv, 768, Dd, 0);

        attn_f16_kernel<<<Bb * Hh, 256, ATTN_SMEM>>>(qkv, ids, ctx);

        gemm_f16_kernel<<<gD, 256>>>(ctx, wot + (long)l*Dd*Dd, bo + l*Dd,
                                     t, Dd, Dd, 0);
        add_ln_kernel<<<NROWS / 8, 256>>>(t, x, h);

        gemm_f16_kernel<<<gF, 256>>>(h, w1t + (long)l*FF*Dd, b1 + l*FF,
                                     f1, FF, Dd, 1);
        gemm_f16_kernel<<<gD, 256>>>(f1, w2t + (long)l*Dd*FF, b2 + l*Dd,
                                     f2, Dd, FF, 0);

        ln_acc_kernel<<<NROWS / 8, 256>>>(f2, x, out);
    }
}

// round 15
// speedup vs baseline: 2.0555x; 1.0560x over previous
#include <cuda_runtime.h>
#include <cuda_fp16.h>
#include <math.h>
#include <stdint.h>

// ---------------- problem constants ----------------
#define Bb   256
#define Ss   256
#define Dd   256
#define Hh   4
#define DHh  64
#define Ll   2
#define FF   1024
#define NROWS (Bb*Ss)           // 65536

// ---------------- scratch (__device__ globals; no allocation) ----------------
__device__ __half g_x0 [NROWS*Dd];     // embed LN output (layer0 input)
__device__ __half g_x1 [NROWS*Dd];     // layer0 output
__device__ __half g_x2 [NROWS*Dd];     // layer1 output
__device__ __half g_qkv[NROWS*768];
__device__ __half g_ctx[NROWS*Dd];
__device__ __half g_hh [NROWS*Dd];     // FFN input
__device__ __half g_f1 [NROWS*FF];
// converted weights (transposed to [N][K], half)
__device__ __half g_wqkvt[Ll*768*Dd];
__device__ __half g_wot  [Ll*Dd*Dd];
__device__ __half g_w1t  [Ll*FF*Dd];
__device__ __half g_w2t  [Ll*Dd*FF];
__device__ float  g_bqkv [Ll*768];

// ---------------- helpers ----------------
__device__ __forceinline__ float gelu_exact(float x) {
    return 0.5f * x * (1.0f + erff(x * 0.70710678118654752440f));
}

__device__ __forceinline__ void mma_f16(float* d, const uint32_t* a, const uint32_t* b) {
    asm volatile(
        "mma.sync.aligned.m16n8k16.row.col.f32.f16.f16.f32 "
        "{%0,%1,%2,%3}, {%4,%5,%6,%7}, {%8,%9}, {%0,%1,%2,%3};"
        : "+f"(d[0]), "+f"(d[1]), "+f"(d[2]), "+f"(d[3])
        : "r"(a[0]), "r"(a[1]), "r"(a[2]), "r"(a[3]), "r"(b[0]), "r"(b[1]));
}

__device__ __forceinline__ uint32_t packh2(float lo, float hi) {
    __half2 h = __floats2half2_rn(lo, hi);
    return *reinterpret_cast<uint32_t*>(&h);
}

// warp-level mean+rstd over 8 values/lane (256-wide row in one warp)
__device__ __forceinline__ float2 warpStats256(const float* v) {
    float s = 0.0f, s2 = 0.0f;
    #pragma unroll
    for (int i = 0; i < 8; i++) { s += v[i]; s2 += v[i] * v[i]; }
    #pragma unroll
    for (int o = 16; o > 0; o >>= 1) {
        s  += __shfl_xor_sync(0xffffffffu, s,  o);
        s2 += __shfl_xor_sync(0xffffffffu, s2, o);
    }
    float mu  = s * (1.0f / 256.0f);
    float var = s2 * (1.0f / 256.0f) - mu * mu;
    return make_float2(mu, rsqrtf(var + 1e-5f));
}

// ---------------- merged weight conversion (ONE launch) ----------------------
__global__ void wconv_all_kernel(
        const float* __restrict__ Wq, const float* __restrict__ Wk,
        const float* __restrict__ Wv, const float* __restrict__ Wo,
        const float* __restrict__ W1, const float* __restrict__ W2,
        const float* __restrict__ bq, const float* __restrict__ bk,
        const float* __restrict__ bv,
        __half* __restrict__ wqkvt, __half* __restrict__ wot,
        __half* __restrict__ w1t,   __half* __restrict__ w2t,
        float* __restrict__ bqkv)
{
    int bid = blockIdx.x;
    int tx = threadIdx.x, ty = threadIdx.y;

    if (bid >= Ll * 768) {                    // bias packing
        int idx = bid - Ll * 768;
        int l = idx / 3, t = idx % 3;
        const float* s = (t == 0) ? bq : (t == 1) ? bk : bv;
        int i = ty * 32 + tx;
        bqkv[l * 768 + t * 256 + i] = s[l * 256 + i];
        return;
    }

    int l = bid / 768, r = bid % 768;
    const float* in; __half* out; int K, N, ti;
    if      (r < 64)  { in = Wq + (long)l*Dd*Dd; out = wqkvt + (long)l*768*Dd;            K = Dd; N = Dd; ti = r; }
    else if (r < 128) { in = Wk + (long)l*Dd*Dd; out = wqkvt + (long)l*768*Dd + 256*Dd;   K = Dd; N = Dd; ti = r - 64; }
    else if (r < 192) { in = Wv + (long)l*Dd*Dd; out = wqkvt + (long)l*768*Dd + 512*Dd;   K = Dd; N = Dd; ti = r - 128; }
    else if (r < 256) { in = Wo + (long)l*Dd*Dd; out = wot + (long)l*Dd*Dd;               K = Dd; N = Dd; ti = r - 192; }
    else if (r < 512) { in = W1 + (long)l*Dd*FF; out = w1t + (long)l*FF*Dd;               K = Dd; N = FF; ti = r - 256; }
    else              { in = W2 + (long)l*FF*Dd; out = w2t + (long)l*Dd*FF;               K = FF; N = Dd; ti = r - 512; }

    int ntx = N / 32;
    int n0 = (ti % ntx) * 32, k0 = (ti / ntx) * 32;

    __shared__ float t[32][33];
    #pragma unroll
    for (int i = 0; i < 32; i += 8)
        t[ty + i][tx] = in[(long)(k0 + ty + i) * N + n0 + tx];
    __syncthreads();
    #pragma unroll
    for (int i = 0; i < 32; i += 8)
        out[(long)(n0 + ty + i) * K + k0 + tx] = __float2half_rn(t[tx][ty + i]);
}

// ---------------- kernel 1: embedding + LN, warp-per-row (half out only) -----
__global__ void __launch_bounds__(256) embed_ln_kernel(
        const int* __restrict__ ids,
        const float* __restrict__ item_emb,
        const float* __restrict__ pos_emb,
        __half* __restrict__ x)
{
    int wid = threadIdx.x >> 5, lane = threadIdx.x & 31;
    int row = blockIdx.x * 8 + wid;
    int s   = row & (Ss - 1);
    int id  = ids[row];
    int c   = lane * 8;

    const float4* ie = (const float4*)(item_emb + (long)id * Dd + c);
    const float4* pe = (const float4*)(pos_emb + s * Dd + c);
    float4 a0 = ie[0], a1 = ie[1], p0 = pe[0], p1 = pe[1];
    float v[8] = {a0.x+p0.x, a0.y+p0.y, a0.z+p0.z, a0.w+p0.w,
                  a1.x+p1.x, a1.y+p1.y, a1.z+p1.z, a1.w+p1.w};
    float2 st = warpStats256(v);
    float y[8];
    #pragma unroll
    for (int i = 0; i < 8; i++) y[i] = (v[i] - st.x) * st.y;

    long o = (long)row * Dd + c;
    uint4 hx;
    hx.x = packh2(y[0], y[1]); hx.y = packh2(y[2], y[3]);
    hx.z = packh2(y[4], y[5]); hx.w = packh2(y[6], y[7]);
    *(uint4*)&x[o] = hx;
}

// ---------------- kernel 2: fp16 GEMM, explicit LDS frags, BK=64 (R12) -------
#define HS 72

__global__ void __launch_bounds__(256, 2) gemm_f16_kernel(
        const __half* __restrict__ A, const __half* __restrict__ Wt,
        const float* __restrict__ bias, __half* __restrict__ C,
        int N, int K, int act)
{
    __shared__ __half As[128 * HS];
    __shared__ __half Bs[128 * HS];

    int tid  = threadIdx.x;
    int w    = tid >> 5, lane = tid & 31;
    int g    = lane >> 2, tig = lane & 3;
    int wm   = w >> 1,  wn = w & 1;
    int rowb = blockIdx.y * 128;
    int colb = blockIdx.x * 128;

    int sr = tid >> 1, sc = (tid & 1) * 32;
    const __half* Ag = A  + (long)(rowb + sr) * K + sc;
    const __half* Wg = Wt + (long)(colb + sr) * K + sc;

    float acc[2][8][4];
    #pragma unroll
    for (int mt = 0; mt < 2; mt++)
        #pragma unroll
        for (int nt = 0; nt < 8; nt++)
            #pragma unroll
            for (int r = 0; r < 4; r++) acc[mt][nt][r] = 0.0f;

    for (int kt = 0; kt < K; kt += 64) {
        __syncthreads();
        #pragma unroll
        for (int i = 0; i < 4; i++)
            *(uint4*)&As[sr * HS + sc + i * 8] = *(const uint4*)(Ag + kt + i * 8);
        #pragma unroll
        for (int i = 0; i < 4; i++)
            *(uint4*)&Bs[sr * HS + sc + i * 8] = *(const uint4*)(Wg + kt + i * 8);
        __syncthreads();

        #pragma unroll
        for (int ks = 0; ks < 4; ks++) {
            int k0 = ks * 16;
            uint32_t a[2][4], b[8][2];
            #pragma unroll
            for (int mt = 0; mt < 2; mt++) {
                int r0 = wm * 32 + mt * 16 + g;
                a[mt][0] = *(const uint32_t*)&As[ r0      * HS + k0 + 2 * tig];
                a[mt][1] = *(const uint32_t*)&As[(r0 + 8) * HS + k0 + 2 * tig];
                a[mt][2] = *(const uint32_t*)&As[ r0      * HS + k0 + 8 + 2 * tig];
                a[mt][3] = *(const uint32_t*)&As[(r0 + 8) * HS + k0 + 8 + 2 * tig];
            }
            #pragma unroll
            for (int nt = 0; nt < 8; nt++) {
                int n = wn * 64 + nt * 8 + g;
                b[nt][0] = *(const uint32_t*)&Bs[n * HS + k0 + 2 * tig];
                b[nt][1] = *(const uint32_t*)&Bs[n * HS + k0 + 8 + 2 * tig];
            }
            #pragma unroll
            for (int mt = 0; mt < 2; mt++)
                #pragma unroll
                for (int nt = 0; nt < 8; nt++)
                    mma_f16(acc[mt][nt], a[mt], b[nt]);
        }
    }

    #pragma unroll
    for (int mt = 0; mt < 2; mt++) {
        int row0 = rowb + wm * 32 + mt * 16 + g;
        #pragma unroll
        for (int nt = 0; nt < 8; nt++) {
            int col = colb + wn * 64 + nt * 8 + 2 * tig;
            float b0 = bias[col], b1 = bias[col + 1];
            float o0 = acc[mt][nt][0] + b0;
            float o1 = acc[mt][nt][1] + b1;
            float o2 = acc[mt][nt][2] + b0;
            float o3 = acc[mt][nt][3] + b1;
            if (act) { o0 = gelu_exact(o0); o1 = gelu_exact(o1);
                       o2 = gelu_exact(o2); o3 = gelu_exact(o3); }
            *(__half2*)&C[(long)row0 * N + col]       = __floats2half2_rn(o0, o1);
            *(__half2*)&C[(long)(row0 + 8) * N + col] = __floats2half2_rn(o2, o3);
        }
    }
}

// ---------------- kernel 2b: fused GEMM + (residual) + LayerNorm -------------
// BM=64, BN=256 (full LN row per block), BK=64. 8 warps 2m x 4n, warp 32x64.
// C = LN(A@Wt^T + bias [+ resid]), half output. N fixed = 256.
// Deterministic cross-warp reduction via smem partials (no atomics).
__global__ void __launch_bounds__(256, 2) gemm_ln_kernel(
        const __half* __restrict__ A, const __half* __restrict__ Wt,
        const float* __restrict__ bias, const __half* __restrict__ resid,
        __half* __restrict__ C, int K)
{
    __shared__ __half As[64 * HS];
    __shared__ __half Bs[256 * HS];
    __shared__ float ps[4][64], ps2[4][64];
    __shared__ float smu[64], srs[64];

    int tid  = threadIdx.x;
    int w    = tid >> 5, lane = tid & 31;
    int g    = lane >> 2, tig = lane & 3;
    int wm   = w >> 2,  wn = w & 3;
    int rowb = blockIdx.x * 64;

    int tr = tid >> 2;             // 0..63
    int tc = (tid & 3) * 16;       // 0/16/32/48
    const __half* Ag = A  + (long)(rowb + tr) * K + tc;
    const __half* Wg = Wt + (long)tr * K + tc;

    float acc[2][8][4];
    #pragma unroll
    for (int mt = 0; mt < 2; mt++)
        #pragma unroll
        for (int nt = 0; nt < 8; nt++)
            #pragma unroll
            for (int r = 0; r < 4; r++) acc[mt][nt][r] = 0.0f;

    for (int kt = 0; kt < K; kt += 64) {
        __syncthreads();
        *(uint4*)&As[tr * HS + tc]     = *(const uint4*)(Ag + kt);
        *(uint4*)&As[tr * HS + tc + 8] = *(const uint4*)(Ag + kt + 8);
        #pragma unroll
        for (int i = 0; i < 4; i++) {
            *(uint4*)&Bs[(tr + 64 * i) * HS + tc]     = *(const uint4*)(Wg + (long)(64 * i) * K + kt);
            *(uint4*)&Bs[(tr + 64 * i) * HS + tc + 8] = *(const uint4*)(Wg + (long)(64 * i) * K + kt + 8);
        }
        __syncthreads();

        #pragma unroll
        for (int ks = 0; ks < 4; ks++) {
            int k0 = ks * 16;
            uint32_t a[2][4], b[8][2];
            #pragma unroll
            for (int mt = 0; mt < 2; mt++) {
                int r0 = wm * 32 + mt * 16 + g;
                a[mt][0] = *(const uint32_t*)&As[ r0      * HS + k0 + 2 * tig];
                a[mt][1] = *(const uint32_t*)&As[(r0 + 8) * HS + k0 + 2 * tig];
                a[mt][2] = *(const uint32_t*)&As[ r0      * HS + k0 + 8 + 2 * tig];
                a[mt][3] = *(const uint32_t*)&As[(r0 + 8) * HS + k0 + 8 + 2 * tig];
            }
            #pragma unroll
            for (int nt = 0; nt < 8; nt++) {
                int n = wn * 64 + nt * 8 + g;
                b[nt][0] = *(const uint32_t*)&Bs[n * HS + k0 + 2 * tig];
                b[nt][1] = *(const uint32_t*)&Bs[n * HS + k0 + 8 + 2 * tig];
            }
            #pragma unroll
            for (int mt = 0; mt < 2; mt++)
                #pragma unroll
                for (int nt = 0; nt < 8; nt++)
                    mma_f16(acc[mt][nt], a[mt], b[nt]);
        }
    }

    // ---- epilogue: bias (+resid) into acc (fp32), row partial stats ----
    float s[4]  = {0.0f, 0.0f, 0.0f, 0.0f};
    float s2[4] = {0.0f, 0.0f, 0.0f, 0.0f};
    #pragma unroll
    for (int mt = 0; mt < 2; mt++) {
        int rl0 = wm * 32 + mt * 16 + g;      // local rows rl0, rl0+8
        #pragma unroll
        for (int nt = 0; nt < 8; nt++) {
            int col = wn * 64 + nt * 8 + 2 * tig;
            float b0 = bias[col], b1 = bias[col + 1];
            float v0 = acc[mt][nt][0] + b0, v1 = acc[mt][nt][1] + b1;
            float v2 = acc[mt][nt][2] + b0, v3 = acc[mt][nt][3] + b1;
            if (resid) {
                float2 ra = __half22float2(*(const __half2*)&resid[(long)(rowb + rl0) * Dd + col]);
                float2 rb = __half22float2(*(const __half2*)&resid[(long)(rowb + rl0 + 8) * Dd + col]);
                v0 += ra.x; v1 += ra.y; v2 += rb.x; v3 += rb.y;
            }
            acc[mt][nt][0] = v0; acc[mt][nt][1] = v1;
            acc[mt][nt][2] = v2; acc[mt][nt][3] = v3;
            s[mt*2]   += v0 + v1;  s2[mt*2]   += v0*v0 + v1*v1;
            s[mt*2+1] += v2 + v3;  s2[mt*2+1] += v2*v2 + v3*v3;
        }
    }
    // reduce across tig group (lane bits 0,1)
    #pragma unroll
    for (int j = 0; j < 4; j++) {
        s[j]  += __shfl_xor_sync(0xffffffffu, s[j],  1);
        s[j]  += __shfl_xor_sync(0xffffffffu, s[j],  2);
        s2[j] += __shfl_xor_sync(0xffffffffu, s2[j], 1);
        s2[j] += __shfl_xor_sync(0xffffffffu, s2[j], 2);
    }
    __syncthreads();   // done with staging smem reads before any epilogue writes? (ps separate arrays; sync orders prior iter) -- safe ordering for ps writes below
    if (tig == 0) {
        #pragma unroll
        for (int j = 0; j < 4; j++) {
            int rl = wm * 32 + (j >> 1) * 16 + (j & 1) * 8 + g;
            ps [wn][rl] = s[j];
            ps2[wn][rl] = s2[j];
        }
    }
    __syncthreads();
    if (tid < 64) {
        float S  = ps [0][tid] + ps [1][tid] + ps [2][tid] + ps [3][tid];
        float S2 = ps2[0][tid] + ps2[1][tid] + ps2[2][tid] + ps2[3][tid];
        float mu  = S * (1.0f / 256.0f);
        float var = S2 * (1.0f / 256.0f) - mu * mu;
        smu[tid] = mu;
        srs[tid] = rsqrtf(var + 1e-5f);
    }
    __syncthreads();

    #pragma unroll
    for (int mt = 0; mt < 2; mt++) {
        int rl0 = wm * 32 + mt * 16 + g;
        float mu0 = smu[rl0],     rs0 = srs[rl0];
        float mu1 = smu[rl0 + 8], rs1 = srs[rl0 + 8];
        #pragma unroll
        for (int nt = 0; nt < 8; nt++) {
            int col = wn * 64 + nt * 8 + 2 * tig;
            *(__half2*)&C[(long)(rowb + rl0) * Dd + col] =
                __floats2half2_rn((acc[mt][nt][0] - mu0) * rs0,
                                  (acc[mt][nt][1] - mu0) * rs0);
            *(__half2*)&C[(long)(rowb + rl0 + 8) * Dd + col] =
                __floats2half2_rn((acc[mt][nt][2] - mu1) * rs1,
                                  (acc[mt][nt][3] - mu1) * rs1);
        }
    }
}

// ---------------- kernel 3: fused fp16 attention, causal-chunked flash -------
#define AS 72
#define VTS 264
#define ATTN_SMEM ((2 * Ss * AS + DHh * VTS) * 2 + Ss * 4)

__global__ void __launch_bounds__(256, 2) attn_f16_kernel(
        const __half* __restrict__ qkv, const int* __restrict__ ids,
        __half* __restrict__ ctx)
{
    extern __shared__ char smraw[];
    __half* sQ  = (__half*)smraw;            // 256 x 72
    __half* sK  = sQ + Ss * AS;              // 256 x 72
    __half* sVt = sK + Ss * AS;              // 64 x 264  (sVt[d][key])
    float* sBias = (float*)(sVt + DHh * VTS);

    int bh = blockIdx.x;
    int b = bh >> 2, h = bh & 3;
    int base = b * Ss, hoff = h * DHh;
    int tid = threadIdx.x;

    for (int idx = tid; idx < Ss * 8; idx += 256) {
        int r = idx >> 3, u = idx & 7;
        const __half* gp = qkv + (long)(base + r) * 768 + hoff + u * 8;
        *(uint4*)&sQ[r * AS + u * 8] = *(const uint4*)(gp);
        *(uint4*)&sK[r * AS + u * 8] = *(const uint4*)(gp + 256);
    }
    for (int idx = tid; idx < Ss * DHh; idx += 256) {
        int r = idx >> 6, d = idx & 63;
        sVt[d * VTS + r] = qkv[(long)(base + r) * 768 + 512 + hoff + d];
    }
    if (tid < Ss) sBias[tid] = (ids[base + tid] > 0) ? 0.0f : -10000.0f;
    __syncthreads();

    int w = tid >> 5, lane = tid & 31;
    int g = lane >> 2, tig = lane & 3;
    const float scale = 0.125f;

    for (int pass = 0; pass < 2; pass++) {
        int m0 = pass * 128 + w * 16;
        int r0 = m0 + g, r1 = m0 + 8 + g;

        uint32_t aS[4][4];
        #pragma unroll
        for (int kc = 0; kc < 4; kc++) {
            int c = kc * 16 + 2 * tig;
            aS[kc][0] = *(const uint32_t*)&sQ[ r0 * AS + c];
            aS[kc][1] = *(const uint32_t*)&sQ[ r1 * AS + c];
            aS[kc][2] = *(const uint32_t*)&sQ[ r0 * AS + c + 8];
            aS[kc][3] = *(const uint32_t*)&sQ[ r1 * AS + c + 8];
        }

        float acc2[8][4];
        #pragma unroll
        for (int nt = 0; nt < 8; nt++)
            #pragma unroll
            for (int r = 0; r < 4; r++) acc2[nt][r] = 0.0f;

        float mrun0 = -1e30f, mrun1 = -1e30f;
        float sum0 = 0.0f, sum1 = 0.0f;

        int nChunks = ((m0 + 15) >> 6) + 1;

        for (int ch = 0; ch < nChunks; ch++) {
            int key0 = ch * 64;

            float s[8][4];
            #pragma unroll
            for (int nt = 0; nt < 8; nt++)
                #pragma unroll
                for (int r = 0; r < 4; r++) s[nt][r] = 0.0f;

            #pragma unroll
            for (int kc = 0; kc < 4; kc++) {
                int c = kc * 16 + 2 * tig;
                #pragma unroll
                for (int nt = 0; nt < 8; nt++) {
                    int n = key0 + nt * 8 + g;
                    uint32_t bb[2];
                    bb[0] = *(const uint32_t*)&sK[n * AS + c];
                    bb[1] = *(const uint32_t*)&sK[n * AS + c + 8];
                    mma_f16(s[nt], aS[kc], bb);
                }
            }

            float cm0 = -1e30f, cm1 = -1e30f;
            #pragma unroll
            for (int nt = 0; nt < 8; nt++) {
                int c0 = key0 + nt * 8 + 2 * tig, c1 = c0 + 1;
                float bp0 = sBias[c0], bp1 = sBias[c1];
                s[nt][0] = s[nt][0] * scale + ((c0 <= r0) ? bp0 : -10000.0f);
                s[nt][1] = s[nt][1] * scale + ((c1 <= r0) ? bp1 : -10000.0f);
                s[nt][2] = s[nt][2] * scale + ((c0 <= r1) ? bp0 : -10000.0f);
                s[nt][3] = s[nt][3] * scale + ((c1 <= r1) ? bp1 : -10000.0f);
                cm0 = fmaxf(cm0, fmaxf(s[nt][0], s[nt][1]));
                cm1 = fmaxf(cm1, fmaxf(s[nt][2], s[nt][3]));
            }
            cm0 = fmaxf(cm0, __shfl_xor_sync(0xffffffffu, cm0, 1));
            cm0 = fmaxf(cm0, __shfl_xor_sync(0xffffffffu, cm0, 2));
            cm1 = fmaxf(cm1, __shfl_xor_sync(0xffffffffu, cm1, 1));
            cm1 = fmaxf(cm1, __shfl_xor_sync(0xffffffffu, cm1, 2));

            float mn0 = fmaxf(mrun0, cm0), mn1 = fmaxf(mrun1, cm1);
            float rs0 = __expf(mrun0 - mn0), rs1 = __expf(mrun1 - mn1);
            sum0 *= rs0; sum1 *= rs1;
            #pragma unroll
            for (int nt = 0; nt < 8; nt++) {
                acc2[nt][0] *= rs0; acc2[nt][1] *= rs0;
                acc2[nt][2] *= rs1; acc2[nt][3] *= rs1;
            }
            mrun0 = mn0; mrun1 = mn1;

            #pragma unroll
            for (int nt = 0; nt < 8; nt++) {
                s[nt][0] = __expf(s[nt][0] - mn0);
                s[nt][1] = __expf(s[nt][1] - mn0);
                s[nt][2] = __expf(s[nt][2] - mn1);
                s[nt][3] = __expf(s[nt][3] - mn1);
                sum0 += s[nt][0] + s[nt][1];
                sum1 += s[nt][2] + s[nt][3];
            }

            #pragma unroll
            for (int kc = 0; kc < 4; kc++) {
                uint32_t a[4];
                a[0] = packh2(s[2*kc][0],   s[2*kc][1]);
                a[1] = packh2(s[2*kc][2],   s[2*kc][3]);
                a[2] = packh2(s[2*kc+1][0], s[2*kc+1][1]);
                a[3] = packh2(s[2*kc+1][2], s[2*kc+1][3]);
                int c = key0 + kc * 16 + 2 * tig;
                #pragma unroll
                for (int nt = 0; nt < 8; nt++) {
                    int d = nt * 8 + g;
                    uint32_t bb[2];
                    bb[0] = *(const uint32_t*)&sVt[d * VTS + c];
                    bb[1] = *(const uint32_t*)&sVt[d * VTS + c + 8];
                    mma_f16(acc2[nt], a, bb);
                }
            }
        }

        sum0 += __shfl_xor_sync(0xffffffffu, sum0, 1);
        sum0 += __shfl_xor_sync(0xffffffffu, sum0, 2);
        sum1 += __shfl_xor_sync(0xffffffffu, sum1, 1);
        sum1 += __shfl_xor_sync(0xffffffffu, sum1, 2);
        float i0 = 1.0f / sum0, i1 = 1.0f / sum1;

        long o0 = (long)(base + r0) * Dd + hoff;
        long o1 = (long)(base + r1) * Dd + hoff;
        #pragma unroll
        for (int nt = 0; nt < 8; nt++) {
            int d = nt * 8 + 2 * tig;
            *(__half2*)&ctx[o0 + d] = __floats2half2_rn(acc2[nt][0] * i0, acc2[nt][1] * i0);
            *(__half2*)&ctx[o1 + d] = __floats2half2_rn(acc2[nt][2] * i1, acc2[nt][3] * i1);
        }
    }
}

// ---------------- kernel 6: out = x0 + x1 + x2 (fp32) ------------------------
__global__ void __launch_bounds__(256) sum3_kernel(
        const __half* __restrict__ x0, const __half* __restrict__ x1,
        const __half* __restrict__ x2, float* __restrict__ out)
{
    long i = ((long)blockIdx.x * 256 + threadIdx.x) * 8;
    uint4 h0 = *(const uint4*)&x0[i];
    uint4 h1 = *(const uint4*)&x1[i];
    uint4 h2 = *(const uint4*)&x2[i];
    const __half2* p0 = (const __half2*)&h0;
    const __half2* p1 = (const __half2*)&h1;
    const __half2* p2 = (const __half2*)&h2;
    float r[8];
    #pragma unroll
    for (int j = 0; j < 4; j++) {
        float2 a = __half22float2(p0[j]);
        float2 b = __half22float2(p1[j]);
        float2 c = __half22float2(p2[j]);
        r[2*j]   = a.x + b.x + c.x;
        r[2*j+1] = a.y + b.y + c.y;
    }
    *(float4*)&out[i]     = make_float4(r[0], r[1], r[2], r[3]);
    *(float4*)&out[i + 4] = make_float4(r[4], r[5], r[6], r[7]);
}

// ---------------- launch ----------------
extern "C" void kernel_launch(void* const* d_in, const int* in_sizes, int n_in,
                              void* d_out, int out_size)
{
    const int*   ids      = (const int*)  d_in[0];
    const float* item_emb = (const float*)d_in[1];
    const float* pos_emb  = (const float*)d_in[2];
    const float* Wq = (const float*)d_in[3];  const float* bq = (const float*)d_in[4];
    const float* Wk = (const float*)d_in[5];  const float* bk = (const float*)d_in[6];
    const float* Wv = (const float*)d_in[7];  const float* bv = (const float*)d_in[8];
    const float* Wo = (const float*)d_in[9];  const float* bo = (const float*)d_in[10];
    const float* W1 = (const float*)d_in[11]; const float* b1 = (const float*)d_in[12];
    const float* W2 = (const float*)d_in[13]; const float* b2 = (const float*)d_in[14];
    float* out = (float*)d_out;

    __half *x0, *x1, *x2, *qkv, *ctx, *h, *f1;
    __half *wqkvt, *wot, *w1t, *w2t;
    float  *bqkv;
    cudaGetSymbolAddress((void**)&x0,    g_x0);
    cudaGetSymbolAddress((void**)&x1,    g_x1);
    cudaGetSymbolAddress((void**)&x2,    g_x2);
    cudaGetSymbolAddress((void**)&qkv,   g_qkv);
    cudaGetSymbolAddress((void**)&ctx,   g_ctx);
    cudaGetSymbolAddress((void**)&h,     g_hh);
    cudaGetSymbolAddress((void**)&f1,    g_f1);
    cudaGetSymbolAddress((void**)&wqkvt, g_wqkvt);
    cudaGetSymbolAddress((void**)&wot,   g_wot);
    cudaGetSymbolAddress((void**)&w1t,   g_w1t);
    cudaGetSymbolAddress((void**)&w2t,   g_w2t);
    cudaGetSymbolAddress((void**)&bqkv,  g_bqkv);

    cudaFuncSetAttribute(attn_f16_kernel,
                         cudaFuncAttributeMaxDynamicSharedMemorySize, ATTN_SMEM);

    wconv_all_kernel<<<Ll * 768 + Ll * 3, dim3(32, 8)>>>(
        Wq, Wk, Wv, Wo, W1, W2, bq, bk, bv, wqkvt, wot, w1t, w2t, bqkv);

    embed_ln_kernel<<<NROWS / 8, 256>>>(ids, item_emb, pos_emb, x0);

    dim3 gQKV(6, 512), gF(8, 512);
    __half* xin = x0;

    for (int l = 0; l < Ll; l++) {
        __half* xout = (l == 0) ? x1 : x2;

        gemm_f16_kernel<<<gQKV, 256>>>(xin, wqkvt + (long)l*768*Dd, bqkv + l*768,
                                       qkv, 768, Dd, 0);

        attn_f16_kernel<<<Bb * Hh, 256, ATTN_SMEM>>>(qkv, ids, ctx);

        // h = LN(ctx@Wo + bo + xin)   (fused)
        gemm_ln_kernel<<<NROWS / 64, 256>>>(ctx, wot + (long)l*Dd*Dd, bo + l*Dd,
                                            xin, h, Dd);

        gemm_f16_kernel<<<gF, 256>>>(h, w1t + (long)l*FF*Dd, b1 + l*FF,
                                     f1, FF, Dd, 1);

        // xout = LN(f1@W2 + b2)   (fused)
        gemm_ln_kernel<<<NROWS / 64, 256>>>(f1, w2t + (long)l*Dd*FF, b2 + l*Dd,
                                            nullptr, xout, FF);

        xin = xout;
    }

    sum3_kernel<<<NROWS * Dd / (256 * 8), 256>>>(x0, x1, x2, out);
}